// round 5
// baseline (speedup 1.0000x reference)
#include <cuda_runtime.h>
#include <cuda_fp16.h>
#include <math.h>
#include <stdint.h>

// Problem constants
#define BB 4
#define LL 1024
#define DD 1024
#define HH 16
#define DK 64
#define MTOT (BB * LL)          // 4096
#define NBL  (BB * LL)          // 4096

// ---------------- scratch (static device memory; no allocations) -------------
__device__ float g_QKV[MTOT * 3 * DD];    // fused Q|K|V, row stride 3072
__device__ float g_M[MTOT * DD];          // merged head outputs
__device__ float g_G[DD * DD];            // M^T M
__device__ float g_mean[DD];
__device__ float g_meanpart[16 * DD];
__device__ float g_partial[DD];
__device__ float g_Gpart[4 * DD * DD];    // syrk split-K partials
__device__ float g_bqkv[3 * DD];

__device__ __align__(16) __half g_xh[MTOT * DD];
__device__ __align__(16) __half g_xl[MTOT * DD];
__device__ __align__(16) __half g_Mh[MTOT * DD];
__device__ __align__(16) __half g_Ml[MTOT * DD];
__device__ __align__(16) __half g_Mth[DD * NBL];
__device__ __align__(16) __half g_Mtl[DD * NBL];
__device__ __align__(16) __half g_Wqkvh[3 * DD * DD];
__device__ __align__(16) __half g_Woh[DD * DD];

// ---------------- small PTX helpers ------------------------------------------
__device__ __forceinline__ uint32_t smem_u32(const void* p) {
    uint32_t a;
    asm("{ .reg .u64 t; cvta.to.shared.u64 t, %1; cvt.u32.u64 %0, t; }"
        : "=r"(a) : "l"(p));
    return a;
}

__device__ __forceinline__ void cp_async16(uint32_t saddr, const void* gptr) {
    asm volatile("cp.async.ca.shared.global [%0], [%1], 16;"
                 :: "r"(saddr), "l"(gptr));
}
__device__ __forceinline__ void cp_commit() {
    asm volatile("cp.async.commit_group;" ::: "memory");
}
template <int N>
__device__ __forceinline__ void cp_wait() {
    asm volatile("cp.async.wait_group %0;" :: "n"(N) : "memory");
}

__device__ __forceinline__ void ldm_x4(uint32_t (&r)[4], uint32_t addr) {
    asm volatile("ldmatrix.sync.aligned.m8n8.x4.shared.b16 {%0,%1,%2,%3}, [%4];"
                 : "=r"(r[0]), "=r"(r[1]), "=r"(r[2]), "=r"(r[3]) : "r"(addr));
}

__device__ __forceinline__ void mma16816(float (&c)[4], const uint32_t (&a)[4],
                                         uint32_t b0, uint32_t b1) {
    asm volatile(
        "mma.sync.aligned.m16n8k16.row.col.f32.f16.f16.f32 "
        "{%0,%1,%2,%3}, {%4,%5,%6,%7}, {%8,%9}, {%0,%1,%2,%3};"
        : "+f"(c[0]), "+f"(c[1]), "+f"(c[2]), "+f"(c[3])
        : "r"(a[0]), "r"(a[1]), "r"(a[2]), "r"(a[3]), "r"(b0), "r"(b1));
}

// packed f32x2 ops (Blackwell)
__device__ __forceinline__ uint64_t fma2(uint64_t a, uint64_t b, uint64_t c) {
    uint64_t d;
    asm("fma.rn.f32x2 %0, %1, %2, %3;" : "=l"(d) : "l"(a), "l"(b), "l"(c));
    return d;
}
__device__ __forceinline__ uint64_t mul2(uint64_t a, uint64_t b) {
    uint64_t d;
    asm("mul.rn.f32x2 %0, %1, %2;" : "=l"(d) : "l"(a), "l"(b));
    return d;
}
__device__ __forceinline__ uint64_t add2(uint64_t a, uint64_t b) {
    uint64_t d;
    asm("add.rn.f32x2 %0, %1, %2;" : "=l"(d) : "l"(a), "l"(b));
    return d;
}
__device__ __forceinline__ uint64_t pack2(float lo, float hi) {
    uint64_t d;
    asm("mov.b64 %0, {%1, %2};" : "=l"(d) : "f"(lo), "f"(hi));
    return d;
}
__device__ __forceinline__ void unpack2(float& lo, float& hi, uint64_t v) {
    asm("mov.b64 {%0, %1}, %2;" : "=f"(lo), "=f"(hi) : "l"(v));
}

// ---------------- bias concat -------------------------------------------------
__global__ __launch_bounds__(256) void biascat_kernel(
    const float* __restrict__ bq, const float* __restrict__ bk,
    const float* __restrict__ bv, float* __restrict__ bqkv)
{
    int i = blockIdx.x * 256 + threadIdx.x;   // 0..3071
    const float* src = (i < DD) ? bq : (i < 2 * DD) ? bk : bv;
    bqkv[i] = src[i & (DD - 1)];
}

// ---------------- fp32 -> (fp16 hi, fp16 lo) split ---------------------------
struct __align__(8) half4 { __half a, b, c, d; };

__global__ __launch_bounds__(256) void split_fp16(
    const float* __restrict__ X, __half* __restrict__ Xh,
    __half* __restrict__ Xl, int n4)
{
    int i = blockIdx.x * 256 + threadIdx.x;
    if (i >= n4) return;
    float4 v = ((const float4*)X)[i];
    __half h0 = __float2half_rn(v.x);
    __half h1 = __float2half_rn(v.y);
    __half h2 = __float2half_rn(v.z);
    __half h3 = __float2half_rn(v.w);
    __half l0 = __float2half_rn(v.x - __half2float(h0));
    __half l1 = __float2half_rn(v.y - __half2float(h1));
    __half l2 = __float2half_rn(v.z - __half2float(h2));
    __half l3 = __float2half_rn(v.w - __half2float(h3));
    half4 hv = {h0, h1, h2, h3};
    half4 lv = {l0, l1, l2, l3};
    ((half4*)Xh)[i] = hv;
    ((half4*)Xl)[i] = lv;
}

__global__ __launch_bounds__(256) void round_fp16(
    const float* __restrict__ X, __half* __restrict__ Xh, int n4)
{
    int i = blockIdx.x * 256 + threadIdx.x;
    if (i >= n4) return;
    float4 v = ((const float4*)X)[i];
    half4 hv = {__float2half_rn(v.x), __float2half_rn(v.y),
                __float2half_rn(v.z), __float2half_rn(v.w)};
    ((half4*)Xh)[i] = hv;
}

// ---------------- transpose + split: M[NBL][DD] -> T[DD][NBL] ----------------
__global__ __launch_bounds__(256) void transpose_split_fp16(
    const float* __restrict__ Msrc,
    __half* __restrict__ Th, __half* __restrict__ Tl)
{
    __shared__ float tile[32][33];
    int bx = blockIdx.x;
    int by = blockIdx.y;
    int tx = threadIdx.x;
    int ty = threadIdx.y;
#pragma unroll
    for (int j = 0; j < 32; j += 8)
        tile[ty + j][tx] = Msrc[(size_t)(by * 32 + ty + j) * DD + bx * 32 + tx];
    __syncthreads();
#pragma unroll
    for (int j = 0; j < 32; j += 8) {
        float v = tile[tx][ty + j];
        __half h = __float2half_rn(v);
        __half l = __float2half_rn(v - __half2float(h));
        size_t off = (size_t)(bx * 32 + ty + j) * NBL + by * 32 + tx;
        Th[off] = h;
        Tl[off] = l;
    }
}

// ---------------- mma.sync GEMM (2-pass fp16 split, 3-stage pipeline) --------
// C[128bm,128bn] = (Ah+Al) @ Bh^T (+bias).  All rows K-major, stride lda.
// gridDim.z = nsplit; split s handles K-range [s*Ksl, (s+1)*Ksl).
// nsplit==1: write C (+bias).  nsplit>1: write Cpart[s*M*N + ...].
#define GPITCH 144              // bytes per smem row (64 fp16 + pad)
#define GTILE  (128 * GPITCH)   // 18432 B
#define GBUF   (2 * GTILE)      // 36864 B per stage
#define GSMEM  (3 * GBUF)       // 3 stages: 110592 B

__global__ __launch_bounds__(256, 2) void gemm2(
    const __half* __restrict__ Ah, const __half* __restrict__ Al,
    const __half* __restrict__ Bh, const float* __restrict__ bias,
    float* __restrict__ C, float* __restrict__ Cpart,
    int lda, int Ksl, int N)
{
    extern __shared__ __align__(16) char smem[];
    const uint32_t sbase = smem_u32(smem);
    const int tid = threadIdx.x;
    const int lane = tid & 31;
    const int wid = tid >> 5;
    const int wm = wid >> 2;
    const int wn = wid & 3;
    const int bx = blockIdx.x;
    const int by = blockIdx.y;
    const int split = blockIdx.z;
    const int nsplit = gridDim.z;
    const int M = gridDim.y * 128;

    const __half* pA[2] = {Ah, Al};
    const int Kc = Ksl >> 6;
    const int total = 2 * Kc;

    float c[4][4][4];
#pragma unroll
    for (int i = 0; i < 4; i++)
#pragma unroll
        for (int j = 0; j < 4; j++)
#pragma unroll
            for (int f = 0; f < 4; f++) c[i][j][f] = 0.0f;

    auto load_chunk = [&](int g, int buf) {
        int p = (g >= Kc) ? 1 : 0;
        int kk = g - p * Kc;
        const __half* Abase = pA[p] + (size_t)by * 128 * lda + split * Ksl + kk * 64;
        const __half* Bbase = Bh + (size_t)bx * 128 * lda + split * Ksl + kk * 64;
        uint32_t aS = sbase + buf * GBUF;
        uint32_t bS = aS + GTILE;
#pragma unroll
        for (int j = 0; j < 4; j++) {
            int lin = tid + j * 256;
            int row = lin >> 3;
            int seg = lin & 7;
            cp_async16(aS + row * GPITCH + seg * 16,
                       Abase + (size_t)row * lda + seg * 8);
            cp_async16(bS + row * GPITCH + seg * 16,
                       Bbase + (size_t)row * lda + seg * 8);
        }
        cp_commit();
    };

    load_chunk(0, 0);
    load_chunk(1, 1);

    int buf = 0;
    for (int g = 0; g < total; g++) {
        if (g == total - 1) cp_wait<0>(); else cp_wait<1>();
        __syncthreads();
        if (g + 2 < total) {
            int nb = buf + 2; if (nb >= 3) nb -= 3;
            load_chunk(g + 2, nb);
        }

        const uint32_t aS = sbase + buf * GBUF;
        const uint32_t bS = aS + GTILE;
#pragma unroll
        for (int s = 0; s < 4; s++) {
            uint32_t a[4][4];
#pragma unroll
            for (int i = 0; i < 4; i++) {
                int row = wm * 64 + i * 16 + (lane & 15);
                ldm_x4(a[i], aS + row * GPITCH + s * 32 + ((lane >> 4) * 16));
            }
            uint32_t b[2][4];
#pragma unroll
            for (int j = 0; j < 2; j++) {
                int row = wn * 32 + j * 16 + ((lane >> 4) << 3) + (lane & 7);
                int off = ((lane >> 3) & 1) * 16;
                ldm_x4(b[j], bS + row * GPITCH + s * 32 + off);
            }
#pragma unroll
            for (int i = 0; i < 4; i++) {
#pragma unroll
                for (int j = 0; j < 2; j++) {
                    mma16816(c[i][2 * j], a[i], b[j][0], b[j][1]);
                    mma16816(c[i][2 * j + 1], a[i], b[j][2], b[j][3]);
                }
            }
        }
        if (++buf == 3) buf = 0;
    }

    float* dst = (nsplit == 1) ? C : (Cpart + (size_t)split * M * N);
    const bool addb = (nsplit == 1) && (bias != nullptr);
#pragma unroll
    for (int i = 0; i < 4; i++) {
        int r0 = by * 128 + wm * 64 + i * 16 + (lane >> 2);
#pragma unroll
        for (int nt = 0; nt < 4; nt++) {
            int col = bx * 128 + wn * 32 + nt * 8 + (lane & 3) * 2;
            float bx0 = 0.0f, bx1 = 0.0f;
            if (addb) { bx0 = bias[col]; bx1 = bias[col + 1]; }
            float2 v0, v1;
            v0.x = c[i][nt][0] + bx0; v0.y = c[i][nt][1] + bx1;
            v1.x = c[i][nt][2] + bx0; v1.y = c[i][nt][3] + bx1;
            *(float2*)(dst + (size_t)r0 * N + col) = v0;
            *(float2*)(dst + (size_t)(r0 + 8) * N + col) = v1;
        }
    }
}

// ---------------- split-K reduce ---------------------------------------------
__global__ __launch_bounds__(256) void reduce_parts(
    const float* __restrict__ parts, int nparts,
    const float* __restrict__ bias, float* __restrict__ out,
    int MN, int N)
{
    int i = blockIdx.x * 256 + threadIdx.x;   // float4 index
    if (i >= MN / 4) return;
    float4 s = ((const float4*)parts)[i];
    for (int p = 1; p < nparts; p++) {
        float4 v = ((const float4*)(parts + (size_t)p * MN))[i];
        s.x += v.x; s.y += v.y; s.z += v.z; s.w += v.w;
    }
    if (bias) {
        int col = (i * 4) % N;
        float4 bv = *(const float4*)(bias + col);
        s.x += bv.x; s.y += bv.y; s.z += bv.z; s.w += bv.w;
    }
    ((float4*)out)[i] = s;
}

// ---------------- Attention: flash-style, f32x2, fused fp16-split epilogue ----
__global__ __launch_bounds__(128) void attn_kernel(
    const float* __restrict__ QKV, float* __restrict__ O,
    __half* __restrict__ Oh, __half* __restrict__ Ol)
{
    __shared__ __align__(16) float Ks[64][64];
    __shared__ __align__(16) float Vs[64][64];

    const int t = threadIdx.x;
    const int qrow = blockIdx.x * 128 + t;
    const int h = blockIdx.y;
    const int b = blockIdx.z;
    const float scale = 0.125f;
    const int RS = 3 * DD;

    const float* qp = QKV + ((size_t)(b * LL + qrow)) * RS + h * DK;
    uint64_t q2[32], acc2[32];
#pragma unroll
    for (int d = 0; d < 16; d++) {
        ulonglong2 v = *(const ulonglong2*)(qp + d * 4);
        q2[2 * d] = v.x; q2[2 * d + 1] = v.y;
        acc2[2 * d] = 0ull; acc2[2 * d + 1] = 0ull;
    }

    float m = -1e30f;
    float l = 0.0f;

    for (int k0 = 0; k0 < LL; k0 += 64) {
        __syncthreads();
        const float* kbase = QKV + ((size_t)(b * LL + k0)) * RS + DD + h * DK;
        const float* vbase = QKV + ((size_t)(b * LL + k0)) * RS + 2 * DD + h * DK;
#pragma unroll
        for (int i = 0; i < 8; i++) {
            int idx = t * 8 + i;
            int row = idx >> 4;
            int c4  = idx & 15;
            *(float4*)&Ks[row][c4 * 4] =
                *(const float4*)(kbase + (size_t)row * RS + c4 * 4);
            *(float4*)&Vs[row][c4 * 4] =
                *(const float4*)(vbase + (size_t)row * RS + c4 * 4);
        }
        __syncthreads();

        for (int kk = 0; kk < 64; kk++) {
            const ulonglong2* kr = (const ulonglong2*)&Ks[kk][0];
            // 4 independent 8-deep chains
            uint64_t c0 = 0ull, c1 = 0ull, c2 = 0ull, c3 = 0ull;
#pragma unroll
            for (int r = 0; r < 8; r++) {
                ulonglong2 kva = kr[r];
                ulonglong2 kvb = kr[r + 8];
                c0 = fma2(q2[2 * r], kva.x, c0);
                c1 = fma2(q2[2 * r + 1], kva.y, c1);
                c2 = fma2(q2[2 * (r + 8)], kvb.x, c2);
                c3 = fma2(q2[2 * (r + 8) + 1], kvb.y, c3);
            }
            float lo, hi;
            unpack2(lo, hi, add2(add2(c0, c1), add2(c2, c3)));
            float s = (lo + hi) * scale;

            if (s > m) {
                float f = __expf(m - s);
                m = s;
                l *= f;
                uint64_t f2 = pack2(f, f);
#pragma unroll
                for (int d = 0; d < 32; d++) acc2[d] = mul2(acc2[d], f2);
            }
            float p = __expf(s - m);
            l += p;
            uint64_t p2 = pack2(p, p);
            const ulonglong2* vr = (const ulonglong2*)&Vs[kk][0];
#pragma unroll
            for (int r = 0; r < 16; r++) {
                ulonglong2 vv = vr[r];
                acc2[2 * r] = fma2(p2, vv.x, acc2[2 * r]);
                acc2[2 * r + 1] = fma2(p2, vv.y, acc2[2 * r + 1]);
            }
        }
    }

    float inv = 1.0f / l;
    uint64_t inv2 = pack2(inv, inv);
    size_t obase = ((size_t)(b * LL + qrow)) * DD + h * DK;
    float* op = O + obase;
    __half* ohp = Oh + obase;
    __half* olp = Ol + obase;
#pragma unroll
    for (int d = 0; d < 16; d++) {
        ulonglong2 o;
        o.x = mul2(acc2[2 * d], inv2);
        o.y = mul2(acc2[2 * d + 1], inv2);
        *(ulonglong2*)(op + d * 4) = o;
        float f0, f1, f2v, f3v;
        unpack2(f0, f1, o.x);
        unpack2(f2v, f3v, o.y);
        __half h0 = __float2half_rn(f0), h1 = __float2half_rn(f1);
        __half h2 = __float2half_rn(f2v), h3 = __float2half_rn(f3v);
        half4 hv = {h0, h1, h2, h3};
        half4 lv = {__float2half_rn(f0 - __half2float(h0)),
                    __float2half_rn(f1 - __half2float(h1)),
                    __float2half_rn(f2v - __half2float(h2)),
                    __float2half_rn(f3v - __half2float(h3))};
        *(half4*)(ohp + d * 4) = hv;
        *(half4*)(olp + d * 4) = lv;
    }
}

// ---------------- column means (two-stage, parallel) --------------------------
__global__ __launch_bounds__(256) void colmean_part(
    const float* __restrict__ M, float* __restrict__ part)
{
    int col = blockIdx.x * 256 + threadIdx.x;   // 0..1023 (grid.x=4)
    int seg = blockIdx.y;                        // 0..15
    float s = 0.0f;
    const float* p = M + (size_t)seg * 256 * DD + col;
#pragma unroll 4
    for (int r = 0; r < 256; r++) s += p[(size_t)r * DD];
    part[seg * DD + col] = s;
}

__global__ __launch_bounds__(256) void colmean_fin(
    const float* __restrict__ part, float* __restrict__ mean)
{
    int col = blockIdx.x * 256 + threadIdx.x;
    float s = 0.0f;
#pragma unroll
    for (int seg = 0; seg < 16; seg++) s += part[seg * DD + col];
    mean[col] = s * (1.0f / (float)NBL);
}

// ---------------- DeCov partial sums (deterministic) -------------------------
__global__ void decov_row(const float* __restrict__ G,
                          const float* __restrict__ mean,
                          float* __restrict__ partial)
{
    __shared__ float red[256];
    const int i = blockIdx.x;
    const float mi = mean[i];
    const float invN = 1.0f / (float)NBL;
    float s = 0.0f;
    for (int j = threadIdx.x; j < DD; j += 256) {
        if (j == i) continue;
        float c = G[(size_t)i * DD + j] * invN - mi * mean[j];
        s += c * c;
    }
    red[threadIdx.x] = s;
    __syncthreads();
    for (int off = 128; off > 0; off >>= 1) {
        if (threadIdx.x < off) red[threadIdx.x] += red[threadIdx.x + off];
        __syncthreads();
    }
    if (threadIdx.x == 0) partial[i] = red[0];
}

__global__ void decov_final(const float* __restrict__ partial, float* __restrict__ out)
{
    __shared__ float red[256];
    float s = 0.0f;
    for (int i = threadIdx.x; i < DD; i += 256) s += partial[i];
    red[threadIdx.x] = s;
    __syncthreads();
    for (int off = 128; off > 0; off >>= 1) {
        if (threadIdx.x < off) red[threadIdx.x] += red[threadIdx.x + off];
        __syncthreads();
    }
    if (threadIdx.x == 0) out[0] = 0.5f * red[0];
}

// ---------------- launch ------------------------------------------------------
extern "C" void kernel_launch(void* const* d_in, const int* in_sizes, int n_in,
                              void* d_out, int out_size)
{
    const float* x  = (const float*)d_in[0];
    const float* Wq = (const float*)d_in[1];
    const float* bq = (const float*)d_in[2];
    const float* Wk = (const float*)d_in[3];
    const float* bk = (const float*)d_in[4];
    const float* Wv = (const float*)d_in[5];
    const float* bv = (const float*)d_in[6];
    const float* Wo = (const float*)d_in[7];
    const float* bo = (const float*)d_in[8];
    float* out = (float*)d_out;

    float *QKVp, *Mp, *Gp, *meanp, *meanpartp, *partp, *Gpart, *bqkv;
    cudaGetSymbolAddress((void**)&QKVp, g_QKV);
    cudaGetSymbolAddress((void**)&Mp, g_M);
    cudaGetSymbolAddress((void**)&Gp, g_G);
    cudaGetSymbolAddress((void**)&meanp, g_mean);
    cudaGetSymbolAddress((void**)&meanpartp, g_meanpart);
    cudaGetSymbolAddress((void**)&partp, g_partial);
    cudaGetSymbolAddress((void**)&Gpart, g_Gpart);
    cudaGetSymbolAddress((void**)&bqkv, g_bqkv);

    __half *xh, *xl, *Mh, *Ml, *Mth, *Mtl, *Wqkvh, *Woh;
    cudaGetSymbolAddress((void**)&xh, g_xh);
    cudaGetSymbolAddress((void**)&xl, g_xl);
    cudaGetSymbolAddress((void**)&Mh, g_Mh);
    cudaGetSymbolAddress((void**)&Ml, g_Ml);
    cudaGetSymbolAddress((void**)&Mth, g_Mth);
    cudaGetSymbolAddress((void**)&Mtl, g_Mtl);
    cudaGetSymbolAddress((void**)&Wqkvh, g_Wqkvh);
    cudaGetSymbolAddress((void**)&Woh, g_Woh);

    cudaFuncSetAttribute(gemm2, cudaFuncAttributeMaxDynamicSharedMemorySize,
                         GSMEM);

    const int n4x = MTOT * DD / 4;      // 1M float4
    const int n4w = DD * DD / 4;        // 256K float4

    // launches 0-4 (so the QKV GEMM is kernel launch #5 for ncu -s 5 -c 1)
    biascat_kernel<<<12, 256>>>(bq, bk, bv, bqkv);                 // 0
    split_fp16<<<n4x / 256, 256>>>(x, xh, xl, n4x);                // 1
    round_fp16<<<n4w / 256, 256>>>(Wq, Wqkvh, n4w);                // 2
    round_fp16<<<n4w / 256, 256>>>(Wk, Wqkvh + DD * DD, n4w);      // 3
    round_fp16<<<n4w / 256, 256>>>(Wv, Wqkvh + 2 * DD * DD, n4w);  // 4

    // fused QKV projection: [4096,1024] @ [3072,1024]^T -> [4096,3072]
    dim3 gQKV(3 * DD / 128, MTOT / 128, 1);   // (24, 32) -> launch 5 (profiled)
    gemm2<<<gQKV, 256, GSMEM>>>(xh, xl, Wqkvh, bqkv, QKVp, nullptr,
                                DD, DD, 3 * DD);

    // attention (writes fp32 M and fused fp16 split Mh/Ml)
    dim3 gAttn(LL / 128, HH, BB);
    attn_kernel<<<gAttn, 128>>>(QKVp, Mp, Mh, Ml);

    // Wo rounding + transposed split of M
    round_fp16<<<n4w / 256, 256>>>(Wo, Woh, n4w);
    transpose_split_fp16<<<dim3(DD / 32, NBL / 32), dim3(32, 8)>>>(Mp, Mth, Mtl);

    // output projection (single wave at 2 CTAs/SM; no split-K)
    dim3 gOut(DD / 128, MTOT / 128, 1);       // (8, 32)
    gemm2<<<gOut, 256, GSMEM>>>(Mh, Ml, Woh, bo, out, nullptr, DD, DD, DD);

    // DeCov path
    colmean_part<<<dim3(4, 16), 256>>>(Mp, meanpartp);
    colmean_fin<<<4, 256>>>(meanpartp, meanp);
    dim3 gSyrk(DD / 128, DD / 128, 4);        // (8, 8, 4)
    gemm2<<<gSyrk, 256, GSMEM>>>(Mth, Mtl, Mth, nullptr, nullptr, Gpart,
                                 NBL, NBL / 4, DD);
    reduce_parts<<<(DD * DD / 4) / 256, 256>>>(Gpart, 4, nullptr, Gp,
                                               DD * DD, DD);
    decov_row<<<DD, 256>>>(Gp, meanp, partp);
    decov_final<<<1, 256>>>(partp, out + (out_size - 1));
}

// round 6
// speedup vs baseline: 2.4400x; 2.4400x over previous
#include <cuda_runtime.h>
#include <cuda_fp16.h>
#include <math.h>
#include <stdint.h>

// Problem constants
#define BB 4
#define LL 1024
#define DD 1024
#define HH 16
#define DK 64
#define MTOT (BB * LL)          // 4096
#define NBL  (BB * LL)          // 4096

// ---------------- scratch (static device memory; no allocations) -------------
__device__ float g_QKV[MTOT * 3 * DD];    // fused Q|K|V, row stride 3072
__device__ float g_M[MTOT * DD];          // merged head outputs
__device__ float g_G[DD * DD];            // M^T M
__device__ float g_mean[DD];
__device__ float g_meanpart[16 * DD];
__device__ float g_partial[DD];
__device__ float g_Gpart[4 * DD * DD];    // syrk split-K partials
__device__ float g_bqkv[3 * DD];

__device__ __align__(16) __half g_xh[MTOT * DD];
__device__ __align__(16) __half g_xl[MTOT * DD];
__device__ __align__(16) __half g_Mh[MTOT * DD];
__device__ __align__(16) __half g_Ml[MTOT * DD];
__device__ __align__(16) __half g_Mth[DD * NBL];
__device__ __align__(16) __half g_Mtl[DD * NBL];
__device__ __align__(16) __half g_Wqkvh[3 * DD * DD];
__device__ __align__(16) __half g_Woh[DD * DD];

// ---------------- small PTX helpers ------------------------------------------
__device__ __forceinline__ uint32_t smem_u32(const void* p) {
    uint32_t a;
    asm("{ .reg .u64 t; cvta.to.shared.u64 t, %1; cvt.u32.u64 %0, t; }"
        : "=r"(a) : "l"(p));
    return a;
}

__device__ __forceinline__ void cp_async16(uint32_t saddr, const void* gptr) {
    asm volatile("cp.async.ca.shared.global [%0], [%1], 16;"
                 :: "r"(saddr), "l"(gptr));
}
__device__ __forceinline__ void cp_commit() {
    asm volatile("cp.async.commit_group;" ::: "memory");
}
template <int N>
__device__ __forceinline__ void cp_wait() {
    asm volatile("cp.async.wait_group %0;" :: "n"(N) : "memory");
}

__device__ __forceinline__ void ldm_x4(uint32_t (&r)[4], uint32_t addr) {
    asm volatile("ldmatrix.sync.aligned.m8n8.x4.shared.b16 {%0,%1,%2,%3}, [%4];"
                 : "=r"(r[0]), "=r"(r[1]), "=r"(r[2]), "=r"(r[3]) : "r"(addr));
}
__device__ __forceinline__ void ldm_x4_trans(uint32_t (&r)[4], uint32_t addr) {
    asm volatile("ldmatrix.sync.aligned.m8n8.x4.trans.shared.b16 {%0,%1,%2,%3}, [%4];"
                 : "=r"(r[0]), "=r"(r[1]), "=r"(r[2]), "=r"(r[3]) : "r"(addr));
}

__device__ __forceinline__ void mma16816(float (&c)[4], const uint32_t (&a)[4],
                                         uint32_t b0, uint32_t b1) {
    asm volatile(
        "mma.sync.aligned.m16n8k16.row.col.f32.f16.f16.f32 "
        "{%0,%1,%2,%3}, {%4,%5,%6,%7}, {%8,%9}, {%0,%1,%2,%3};"
        : "+f"(c[0]), "+f"(c[1]), "+f"(c[2]), "+f"(c[3])
        : "r"(a[0]), "r"(a[1]), "r"(a[2]), "r"(a[3]), "r"(b0), "r"(b1));
}

__device__ __forceinline__ uint32_t pack_h2(__half x, __half y) {
    __half2 h = __halves2half2(x, y);
    return *(uint32_t*)&h;
}

// ---------------- bias concat -------------------------------------------------
__global__ __launch_bounds__(256) void biascat_kernel(
    const float* __restrict__ bq, const float* __restrict__ bk,
    const float* __restrict__ bv, float* __restrict__ bqkv)
{
    int i = blockIdx.x * 256 + threadIdx.x;   // 0..3071
    const float* src = (i < DD) ? bq : (i < 2 * DD) ? bk : bv;
    bqkv[i] = src[i & (DD - 1)];
}

// ---------------- fp32 -> (fp16 hi, fp16 lo) split ---------------------------
struct __align__(8) half4 { __half a, b, c, d; };

__global__ __launch_bounds__(256) void split_fp16(
    const float* __restrict__ X, __half* __restrict__ Xh,
    __half* __restrict__ Xl, int n4)
{
    int i = blockIdx.x * 256 + threadIdx.x;
    if (i >= n4) return;
    float4 v = ((const float4*)X)[i];
    __half h0 = __float2half_rn(v.x);
    __half h1 = __float2half_rn(v.y);
    __half h2 = __float2half_rn(v.z);
    __half h3 = __float2half_rn(v.w);
    __half l0 = __float2half_rn(v.x - __half2float(h0));
    __half l1 = __float2half_rn(v.y - __half2float(h1));
    __half l2 = __float2half_rn(v.z - __half2float(h2));
    __half l3 = __float2half_rn(v.w - __half2float(h3));
    half4 hv = {h0, h1, h2, h3};
    half4 lv = {l0, l1, l2, l3};
    ((half4*)Xh)[i] = hv;
    ((half4*)Xl)[i] = lv;
}

__global__ __launch_bounds__(256) void round_fp16(
    const float* __restrict__ X, __half* __restrict__ Xh, int n4)
{
    int i = blockIdx.x * 256 + threadIdx.x;
    if (i >= n4) return;
    float4 v = ((const float4*)X)[i];
    half4 hv = {__float2half_rn(v.x), __float2half_rn(v.y),
                __float2half_rn(v.z), __float2half_rn(v.w)};
    ((half4*)Xh)[i] = hv;
}

// ---------------- transpose + split: M[NBL][DD] -> T[DD][NBL] ----------------
__global__ __launch_bounds__(256) void transpose_split_fp16(
    const float* __restrict__ Msrc,
    __half* __restrict__ Th, __half* __restrict__ Tl)
{
    __shared__ float tile[32][33];
    int bx = blockIdx.x;
    int by = blockIdx.y;
    int tx = threadIdx.x;
    int ty = threadIdx.y;
#pragma unroll
    for (int j = 0; j < 32; j += 8)
        tile[ty + j][tx] = Msrc[(size_t)(by * 32 + ty + j) * DD + bx * 32 + tx];
    __syncthreads();
#pragma unroll
    for (int j = 0; j < 32; j += 8) {
        float v = tile[tx][ty + j];
        __half h = __float2half_rn(v);
        __half l = __float2half_rn(v - __half2float(h));
        size_t off = (size_t)(bx * 32 + ty + j) * NBL + by * 32 + tx;
        Th[off] = h;
        Tl[off] = l;
    }
}

// ---------------- mma.sync GEMM (2-pass fp16 split, 3-stage pipeline) --------
#define GPITCH 144              // bytes per smem row (64 fp16 + pad)
#define GTILE  (128 * GPITCH)   // 18432 B
#define GBUF   (2 * GTILE)      // 36864 B per stage
#define GSMEM  (3 * GBUF)       // 3 stages: 110592 B

__global__ __launch_bounds__(256) void gemm2(
    const __half* __restrict__ Ah, const __half* __restrict__ Al,
    const __half* __restrict__ Bh, const float* __restrict__ bias,
    float* __restrict__ C, float* __restrict__ Cpart,
    int lda, int Ksl, int N)
{
    extern __shared__ __align__(16) char smem[];
    const uint32_t sbase = smem_u32(smem);
    const int tid = threadIdx.x;
    const int lane = tid & 31;
    const int wid = tid >> 5;
    const int wm = wid >> 2;
    const int wn = wid & 3;
    const int bx = blockIdx.x;
    const int by = blockIdx.y;
    const int split = blockIdx.z;
    const int nsplit = gridDim.z;
    const int M = gridDim.y * 128;

    const __half* pA[2] = {Ah, Al};
    const int Kc = Ksl >> 6;
    const int total = 2 * Kc;

    float c[4][4][4];
#pragma unroll
    for (int i = 0; i < 4; i++)
#pragma unroll
        for (int j = 0; j < 4; j++)
#pragma unroll
            for (int f = 0; f < 4; f++) c[i][j][f] = 0.0f;

    auto load_chunk = [&](int g, int buf) {
        int p = (g >= Kc) ? 1 : 0;
        int kk = g - p * Kc;
        const __half* Abase = pA[p] + (size_t)by * 128 * lda + split * Ksl + kk * 64;
        const __half* Bbase = Bh + (size_t)bx * 128 * lda + split * Ksl + kk * 64;
        uint32_t aS = sbase + buf * GBUF;
        uint32_t bS = aS + GTILE;
#pragma unroll
        for (int j = 0; j < 4; j++) {
            int lin = tid + j * 256;
            int row = lin >> 3;
            int seg = lin & 7;
            cp_async16(aS + row * GPITCH + seg * 16,
                       Abase + (size_t)row * lda + seg * 8);
            cp_async16(bS + row * GPITCH + seg * 16,
                       Bbase + (size_t)row * lda + seg * 8);
        }
        cp_commit();
    };

    load_chunk(0, 0);
    load_chunk(1, 1);

    int buf = 0;
    for (int g = 0; g < total; g++) {
        if (g == total - 1) cp_wait<0>(); else cp_wait<1>();
        __syncthreads();
        if (g + 2 < total) {
            int nb = buf + 2; if (nb >= 3) nb -= 3;
            load_chunk(g + 2, nb);
        }

        const uint32_t aS = sbase + buf * GBUF;
        const uint32_t bS = aS + GTILE;
#pragma unroll
        for (int s = 0; s < 4; s++) {
            uint32_t a[4][4];
#pragma unroll
            for (int i = 0; i < 4; i++) {
                int row = wm * 64 + i * 16 + (lane & 15);
                ldm_x4(a[i], aS + row * GPITCH + s * 32 + ((lane >> 4) * 16));
            }
            uint32_t b[2][4];
#pragma unroll
            for (int j = 0; j < 2; j++) {
                int row = wn * 32 + j * 16 + ((lane >> 4) << 3) + (lane & 7);
                int off = ((lane >> 3) & 1) * 16;
                ldm_x4(b[j], bS + row * GPITCH + s * 32 + off);
            }
#pragma unroll
            for (int i = 0; i < 4; i++) {
#pragma unroll
                for (int j = 0; j < 2; j++) {
                    mma16816(c[i][2 * j], a[i], b[j][0], b[j][1]);
                    mma16816(c[i][2 * j + 1], a[i], b[j][2], b[j][3]);
                }
            }
        }
        if (++buf == 3) buf = 0;
    }

    float* dst = (nsplit == 1) ? C : (Cpart + (size_t)split * M * N);
    const bool addb = (nsplit == 1) && (bias != nullptr);
#pragma unroll
    for (int i = 0; i < 4; i++) {
        int r0 = by * 128 + wm * 64 + i * 16 + (lane >> 2);
#pragma unroll
        for (int nt = 0; nt < 4; nt++) {
            int col = bx * 128 + wn * 32 + nt * 8 + (lane & 3) * 2;
            float bx0 = 0.0f, bx1 = 0.0f;
            if (addb) { bx0 = bias[col]; bx1 = bias[col + 1]; }
            float2 v0, v1;
            v0.x = c[i][nt][0] + bx0; v0.y = c[i][nt][1] + bx1;
            v1.x = c[i][nt][2] + bx0; v1.y = c[i][nt][3] + bx1;
            *(float2*)(dst + (size_t)r0 * N + col) = v0;
            *(float2*)(dst + (size_t)(r0 + 8) * N + col) = v1;
        }
    }
}

// ---------------- split-K reduce ---------------------------------------------
__global__ __launch_bounds__(256) void reduce_parts(
    const float* __restrict__ parts, int nparts,
    const float* __restrict__ bias, float* __restrict__ out,
    int MN, int N)
{
    int i = blockIdx.x * 256 + threadIdx.x;   // float4 index
    if (i >= MN / 4) return;
    float4 s = ((const float4*)parts)[i];
    for (int p = 1; p < nparts; p++) {
        float4 v = ((const float4*)(parts + (size_t)p * MN))[i];
        s.x += v.x; s.y += v.y; s.z += v.z; s.w += v.w;
    }
    if (bias) {
        int col = (i * 4) % N;
        float4 bv = *(const float4*)(bias + col);
        s.x += bv.x; s.y += bv.y; s.z += bv.z; s.w += bv.w;
    }
    ((float4*)out)[i] = s;
}

// ---------------- Attention: flash + mma.sync fp16 with splits ----------------
// 128 queries per CTA, 8 warps (each owns m16 rows). 64-key tiles in smem.
// S = Qh*Kh + Ql*Kh + Qh*Kl (0.125 folded into Q; fp32 accum)
// O = Ph*Vh + Pl*Vh + Ph*Vl  (P from softmax'd S fragments)
#define AP 72                   // fp16 pitch (elements)
#define APB 144                 // bytes

__global__ __launch_bounds__(256) void attn_mma(
    const float* __restrict__ QKV, float* __restrict__ O,
    __half* __restrict__ Oh, __half* __restrict__ Ol)
{
    __shared__ __align__(16) __half KhS[64 * AP];
    __shared__ __align__(16) __half KlS[64 * AP];
    __shared__ __align__(16) __half VhS[64 * AP];
    __shared__ __align__(16) __half VlS[64 * AP];

    const int tid = threadIdx.x;
    const int lane = tid & 31;
    const int w = tid >> 5;
    const int q0 = blockIdx.x * 128;
    const int h = blockIdx.y;
    const int b = blockIdx.z;
    const int RS = 3 * DD;
    const uint32_t khs = smem_u32(KhS), kls = smem_u32(KlS);
    const uint32_t vhs = smem_u32(VhS), vls = smem_u32(VlS);

    // Q fragments (0.125 folded in; hi/lo fp16 split)
    uint32_t Qah[4][4], Qal[4][4];
    {
        int r0 = b * LL + q0 + w * 16 + (lane >> 2);
        int cb = h * DK + (lane & 3) * 2;
#pragma unroll
        for (int s = 0; s < 4; s++)
#pragma unroll
            for (int t = 0; t < 4; t++) {
                int rr = r0 + (t & 1) * 8;
                int cc = cb + s * 16 + (t >> 1) * 8;
                float2 v = *(const float2*)(QKV + (size_t)rr * RS + cc);
                v.x *= 0.125f; v.y *= 0.125f;
                __half hx = __float2half_rn(v.x), hy = __float2half_rn(v.y);
                __half lx = __float2half_rn(v.x - __half2float(hx));
                __half ly = __float2half_rn(v.y - __half2float(hy));
                Qah[s][t] = pack_h2(hx, hy);
                Qal[s][t] = pack_h2(lx, ly);
            }
    }

    float m0 = -1e30f, m1 = -1e30f, l0 = 0.0f, l1 = 0.0f;
    float co[8][4];
#pragma unroll
    for (int j = 0; j < 8; j++)
#pragma unroll
        for (int f = 0; f < 4; f++) co[j][f] = 0.0f;

    for (int kt = 0; kt < LL; kt += 64) {
        __syncthreads();
        // load + split K/V tile (64 keys x 64 dims fp32 -> fp16 h/l)
#pragma unroll
        for (int it = 0; it < 4; it++) {
            int lin = tid + it * 256;       // 0..1023
            int row = lin >> 4;
            int c4 = lin & 15;
            const float* kp = QKV + (size_t)(b * LL + kt + row) * RS + DD + h * DK + c4 * 4;
            float4 kv = *(const float4*)kp;
            float4 vv = *(const float4*)(kp + DD);
            __half k0 = __float2half_rn(kv.x), k1 = __float2half_rn(kv.y);
            __half k2 = __float2half_rn(kv.z), k3 = __float2half_rn(kv.w);
            half4 khv = {k0, k1, k2, k3};
            half4 klv = {__float2half_rn(kv.x - __half2float(k0)),
                         __float2half_rn(kv.y - __half2float(k1)),
                         __float2half_rn(kv.z - __half2float(k2)),
                         __float2half_rn(kv.w - __half2float(k3))};
            __half v0 = __float2half_rn(vv.x), v1 = __float2half_rn(vv.y);
            __half v2 = __float2half_rn(vv.z), v3 = __float2half_rn(vv.w);
            half4 vhv = {v0, v1, v2, v3};
            half4 vlv = {__float2half_rn(vv.x - __half2float(v0)),
                         __float2half_rn(vv.y - __half2float(v1)),
                         __float2half_rn(vv.z - __half2float(v2)),
                         __float2half_rn(vv.w - __half2float(v3))};
            int off = row * AP + c4 * 4;
            *(half4*)(KhS + off) = khv;
            *(half4*)(KlS + off) = klv;
            *(half4*)(VhS + off) = vhv;
            *(half4*)(VlS + off) = vlv;
        }
        __syncthreads();

        // ---- QK: S tile 16x64 per warp ----
        float sc[8][4];
#pragma unroll
        for (int j = 0; j < 8; j++)
#pragma unroll
            for (int f = 0; f < 4; f++) sc[j][f] = 0.0f;

#pragma unroll
        for (int s = 0; s < 4; s++) {
#pragma unroll
            for (int j = 0; j < 4; j++) {
                uint32_t roff = (j * 16 + ((lane >> 4) << 3) + (lane & 7)) * APB
                              + s * 32 + ((lane >> 3) & 1) * 16;
                uint32_t bh[4], bl[4];
                ldm_x4(bh, khs + roff);
                ldm_x4(bl, kls + roff);
                mma16816(sc[2 * j],     Qah[s], bh[0], bh[1]);
                mma16816(sc[2 * j + 1], Qah[s], bh[2], bh[3]);
                mma16816(sc[2 * j],     Qal[s], bh[0], bh[1]);
                mma16816(sc[2 * j + 1], Qal[s], bh[2], bh[3]);
                mma16816(sc[2 * j],     Qah[s], bl[0], bl[1]);
                mma16816(sc[2 * j + 1], Qah[s], bl[2], bl[3]);
            }
        }

        // ---- online softmax (2 rows per thread) ----
        float t0 = -1e30f, t1 = -1e30f;
#pragma unroll
        for (int j = 0; j < 8; j++) {
            t0 = fmaxf(t0, fmaxf(sc[j][0], sc[j][1]));
            t1 = fmaxf(t1, fmaxf(sc[j][2], sc[j][3]));
        }
        t0 = fmaxf(t0, __shfl_xor_sync(0xffffffffu, t0, 1));
        t0 = fmaxf(t0, __shfl_xor_sync(0xffffffffu, t0, 2));
        t1 = fmaxf(t1, __shfl_xor_sync(0xffffffffu, t1, 1));
        t1 = fmaxf(t1, __shfl_xor_sync(0xffffffffu, t1, 2));
        float mn0 = fmaxf(m0, t0), mn1 = fmaxf(m1, t1);
        float f0 = __expf(m0 - mn0), f1 = __expf(m1 - mn1);
        float rs0 = 0.0f, rs1 = 0.0f;
#pragma unroll
        for (int j = 0; j < 8; j++) {
            sc[j][0] = __expf(sc[j][0] - mn0);
            sc[j][1] = __expf(sc[j][1] - mn0);
            sc[j][2] = __expf(sc[j][2] - mn1);
            sc[j][3] = __expf(sc[j][3] - mn1);
            rs0 += sc[j][0] + sc[j][1];
            rs1 += sc[j][2] + sc[j][3];
        }
        rs0 += __shfl_xor_sync(0xffffffffu, rs0, 1);
        rs0 += __shfl_xor_sync(0xffffffffu, rs0, 2);
        rs1 += __shfl_xor_sync(0xffffffffu, rs1, 1);
        rs1 += __shfl_xor_sync(0xffffffffu, rs1, 2);
        l0 = l0 * f0 + rs0;
        l1 = l1 * f1 + rs1;
        m0 = mn0; m1 = mn1;
#pragma unroll
        for (int j = 0; j < 8; j++) {
            co[j][0] *= f0; co[j][1] *= f0;
            co[j][2] *= f1; co[j][3] *= f1;
        }

        // ---- PV: O += P @ V ----
#pragma unroll
        for (int s = 0; s < 4; s++) {
            // A fragments from P blocks 2s, 2s+1
            uint32_t pah[4], pal[4];
#pragma unroll
            for (int t = 0; t < 4; t++) {
                int bk = 2 * s + (t >> 1);
                float p0 = sc[bk][(t & 1) * 2];
                float p1 = sc[bk][(t & 1) * 2 + 1];
                __half h0 = __float2half_rn(p0), h1 = __float2half_rn(p1);
                pah[t] = pack_h2(h0, h1);
                pal[t] = pack_h2(__float2half_rn(p0 - __half2float(h0)),
                                 __float2half_rn(p1 - __half2float(h1)));
            }
#pragma unroll
            for (int j = 0; j < 4; j++) {
                uint32_t roff = (s * 16 + ((lane >> 3) & 1) * 8 + (lane & 7)) * APB
                              + (j * 16 + ((lane >> 4) & 1) * 8) * 2;
                uint32_t vbh[4], vbl[4];
                ldm_x4_trans(vbh, vhs + roff);
                ldm_x4_trans(vbl, vls + roff);
                mma16816(co[2 * j],     pah, vbh[0], vbh[1]);
                mma16816(co[2 * j + 1], pah, vbh[2], vbh[3]);
                mma16816(co[2 * j],     pal, vbh[0], vbh[1]);
                mma16816(co[2 * j + 1], pal, vbh[2], vbh[3]);
                mma16816(co[2 * j],     pah, vbl[0], vbl[1]);
                mma16816(co[2 * j + 1], pah, vbl[2], vbl[3]);
            }
        }
    }

    // epilogue: normalize + fp32 + fp16 h/l outputs
    float inv0 = 1.0f / l0, inv1 = 1.0f / l1;
    int grow = q0 + w * 16 + (lane >> 2);
    size_t base0 = (size_t)(b * LL + grow) * DD + h * DK;
    size_t base1 = base0 + (size_t)8 * DD;
#pragma unroll
    for (int j = 0; j < 8; j++) {
        int col = j * 8 + (lane & 3) * 2;
        float a0 = co[j][0] * inv0, a1 = co[j][1] * inv0;
        float a2 = co[j][2] * inv1, a3 = co[j][3] * inv1;
        float2 w0 = {a0, a1}, w1 = {a2, a3};
        *(float2*)(O + base0 + col) = w0;
        *(float2*)(O + base1 + col) = w1;
        __half h0 = __float2half_rn(a0), h1 = __float2half_rn(a1);
        __half h2 = __float2half_rn(a2), h3 = __float2half_rn(a3);
        __half2 hh0 = __halves2half2(h0, h1);
        __half2 hh1 = __halves2half2(h2, h3);
        *(__half2*)(Oh + base0 + col) = hh0;
        *(__half2*)(Oh + base1 + col) = hh1;
        __half2 ll0v = __halves2half2(__float2half_rn(a0 - __half2float(h0)),
                                      __float2half_rn(a1 - __half2float(h1)));
        __half2 ll1v = __halves2half2(__float2half_rn(a2 - __half2float(h2)),
                                      __float2half_rn(a3 - __half2float(h3)));
        *(__half2*)(Ol + base0 + col) = ll0v;
        *(__half2*)(Ol + base1 + col) = ll1v;
    }
}

// ---------------- column means (two-stage, parallel) --------------------------
__global__ __launch_bounds__(256) void colmean_part(
    const float* __restrict__ M, float* __restrict__ part)
{
    int col = blockIdx.x * 256 + threadIdx.x;
    int seg = blockIdx.y;
    float s = 0.0f;
    const float* p = M + (size_t)seg * 256 * DD + col;
#pragma unroll 4
    for (int r = 0; r < 256; r++) s += p[(size_t)r * DD];
    part[seg * DD + col] = s;
}

__global__ __launch_bounds__(256) void colmean_fin(
    const float* __restrict__ part, float* __restrict__ mean)
{
    int col = blockIdx.x * 256 + threadIdx.x;
    float s = 0.0f;
#pragma unroll
    for (int seg = 0; seg < 16; seg++) s += part[seg * DD + col];
    mean[col] = s * (1.0f / (float)NBL);
}

// ---------------- DeCov partial sums (deterministic) -------------------------
__global__ void decov_row(const float* __restrict__ G,
                          const float* __restrict__ mean,
                          float* __restrict__ partial)
{
    __shared__ float red[256];
    const int i = blockIdx.x;
    const float mi = mean[i];
    const float invN = 1.0f / (float)NBL;
    float s = 0.0f;
    for (int j = threadIdx.x; j < DD; j += 256) {
        if (j == i) continue;
        float c = G[(size_t)i * DD + j] * invN - mi * mean[j];
        s += c * c;
    }
    red[threadIdx.x] = s;
    __syncthreads();
    for (int off = 128; off > 0; off >>= 1) {
        if (threadIdx.x < off) red[threadIdx.x] += red[threadIdx.x + off];
        __syncthreads();
    }
    if (threadIdx.x == 0) partial[i] = red[0];
}

__global__ void decov_final(const float* __restrict__ partial, float* __restrict__ out)
{
    __shared__ float red[256];
    float s = 0.0f;
    for (int i = threadIdx.x; i < DD; i += 256) s += partial[i];
    red[threadIdx.x] = s;
    __syncthreads();
    for (int off = 128; off > 0; off >>= 1) {
        if (threadIdx.x < off) red[threadIdx.x] += red[threadIdx.x + off];
        __syncthreads();
    }
    if (threadIdx.x == 0) out[0] = 0.5f * red[0];
}

// ---------------- launch ------------------------------------------------------
extern "C" void kernel_launch(void* const* d_in, const int* in_sizes, int n_in,
                              void* d_out, int out_size)
{
    const float* x  = (const float*)d_in[0];
    const float* Wq = (const float*)d_in[1];
    const float* bq = (const float*)d_in[2];
    const float* Wk = (const float*)d_in[3];
    const float* bk = (const float*)d_in[4];
    const float* Wv = (const float*)d_in[5];
    const float* bv = (const float*)d_in[6];
    const float* Wo = (const float*)d_in[7];
    const float* bo = (const float*)d_in[8];
    float* out = (float*)d_out;

    float *QKVp, *Mp, *Gp, *meanp, *meanpartp, *partp, *Gpart, *bqkv;
    cudaGetSymbolAddress((void**)&QKVp, g_QKV);
    cudaGetSymbolAddress((void**)&Mp, g_M);
    cudaGetSymbolAddress((void**)&Gp, g_G);
    cudaGetSymbolAddress((void**)&meanp, g_mean);
    cudaGetSymbolAddress((void**)&meanpartp, g_meanpart);
    cudaGetSymbolAddress((void**)&partp, g_partial);
    cudaGetSymbolAddress((void**)&Gpart, g_Gpart);
    cudaGetSymbolAddress((void**)&bqkv, g_bqkv);

    __half *xh, *xl, *Mh, *Ml, *Mth, *Mtl, *Wqkvh, *Woh;
    cudaGetSymbolAddress((void**)&xh, g_xh);
    cudaGetSymbolAddress((void**)&xl, g_xl);
    cudaGetSymbolAddress((void**)&Mh, g_Mh);
    cudaGetSymbolAddress((void**)&Ml, g_Ml);
    cudaGetSymbolAddress((void**)&Mth, g_Mth);
    cudaGetSymbolAddress((void**)&Mtl, g_Mtl);
    cudaGetSymbolAddress((void**)&Wqkvh, g_Wqkvh);
    cudaGetSymbolAddress((void**)&Woh, g_Woh);

    cudaFuncSetAttribute(gemm2, cudaFuncAttributeMaxDynamicSharedMemorySize,
                         GSMEM);

    const int n4x = MTOT * DD / 4;      // 1M float4
    const int n4w = DD * DD / 4;        // 256K float4

    biascat_kernel<<<12, 256>>>(bq, bk, bv, bqkv);
    split_fp16<<<n4x / 256, 256>>>(x, xh, xl, n4x);
    round_fp16<<<n4w / 256, 256>>>(Wq, Wqkvh, n4w);
    round_fp16<<<n4w / 256, 256>>>(Wk, Wqkvh + DD * DD, n4w);
    round_fp16<<<n4w / 256, 256>>>(Wv, Wqkvh + 2 * DD * DD, n4w);

    // fused QKV projection: [4096,1024] @ [3072,1024]^T -> [4096,3072]
    dim3 gQKV(3 * DD / 128, MTOT / 128, 1);   // (24, 32)
    gemm2<<<gQKV, 256, GSMEM>>>(xh, xl, Wqkvh, bqkv, QKVp, nullptr,
                                DD, DD, 3 * DD);

    // attention (tensor-core flash; writes fp32 M and fused fp16 split Mh/Ml)
    dim3 gAttn(LL / 128, HH, BB);              // (8, 16, 4)
    attn_mma<<<gAttn, 256>>>(QKVp, Mp, Mh, Ml);

    // Wo rounding + transposed split of M
    round_fp16<<<n4w / 256, 256>>>(Wo, Woh, n4w);
    transpose_split_fp16<<<dim3(DD / 32, NBL / 32), dim3(32, 8)>>>(Mp, Mth, Mtl);

    // output projection
    dim3 gOut(DD / 128, MTOT / 128, 1);       // (8, 32)
    gemm2<<<gOut, 256, GSMEM>>>(Mh, Ml, Woh, bo, out, nullptr, DD, DD, DD);

    // DeCov path
    colmean_part<<<dim3(4, 16), 256>>>(Mp, meanpartp);
    colmean_fin<<<4, 256>>>(meanpartp, meanp);
    dim3 gSyrk(DD / 128, DD / 128, 4);        // (8, 8, 4)
    gemm2<<<gSyrk, 256, GSMEM>>>(Mth, Mtl, Mth, nullptr, nullptr, Gpart,
                                 NBL, NBL / 4, DD);
    reduce_parts<<<(DD * DD / 4) / 256, 256>>>(Gpart, 4, nullptr, Gp,
                                               DD * DD, DD);
    decov_row<<<DD, 256>>>(Gp, meanp, partp);
    decov_final<<<1, 256>>>(partp, out + (out_size - 1));
}

// round 7
// speedup vs baseline: 2.5161x; 1.0312x over previous
#include <cuda_runtime.h>
#include <cuda_fp16.h>
#include <math.h>
#include <stdint.h>

// Problem constants
#define BB 4
#define LL 1024
#define DD 1024
#define HH 16
#define DK 64
#define MTOT (BB * LL)          // 4096
#define NBL  (BB * LL)          // 4096
#define RS3  (3 * DD)           // 3072

// ---------------- scratch (static device memory; no allocations) -------------
__device__ float g_G[DD * DD];            // M^T M
__device__ float g_mean[DD];
__device__ float g_meanpart[16 * DD];
__device__ float g_partial[DD];
__device__ float g_Gpart[4 * DD * DD];    // syrk split-K partials
__device__ float g_bqkv[3 * DD];

__device__ __align__(16) __half g_QKVh[MTOT * RS3];   // hi split (Q scaled by 1/8)
__device__ __align__(16) __half g_QKVl[MTOT * RS3];   // lo split
__device__ __align__(16) __half g_xh[MTOT * DD];
__device__ __align__(16) __half g_xl[MTOT * DD];
__device__ __align__(16) __half g_Mh[MTOT * DD];
__device__ __align__(16) __half g_Ml[MTOT * DD];
__device__ __align__(16) __half g_Mth[DD * NBL];
__device__ __align__(16) __half g_Mtl[DD * NBL];
__device__ __align__(16) __half g_Wqkvh[3 * DD * DD];
__device__ __align__(16) __half g_Woh[DD * DD];

// ---------------- small PTX helpers ------------------------------------------
__device__ __forceinline__ uint32_t smem_u32(const void* p) {
    uint32_t a;
    asm("{ .reg .u64 t; cvta.to.shared.u64 t, %1; cvt.u32.u64 %0, t; }"
        : "=r"(a) : "l"(p));
    return a;
}

__device__ __forceinline__ void cp_async16(uint32_t saddr, const void* gptr) {
    asm volatile("cp.async.ca.shared.global [%0], [%1], 16;"
                 :: "r"(saddr), "l"(gptr));
}
__device__ __forceinline__ void cp_commit() {
    asm volatile("cp.async.commit_group;" ::: "memory");
}
template <int N>
__device__ __forceinline__ void cp_wait() {
    asm volatile("cp.async.wait_group %0;" :: "n"(N) : "memory");
}

__device__ __forceinline__ void ldm_x4(uint32_t (&r)[4], uint32_t addr) {
    asm volatile("ldmatrix.sync.aligned.m8n8.x4.shared.b16 {%0,%1,%2,%3}, [%4];"
                 : "=r"(r[0]), "=r"(r[1]), "=r"(r[2]), "=r"(r[3]) : "r"(addr));
}
__device__ __forceinline__ void ldm_x4_trans(uint32_t (&r)[4], uint32_t addr) {
    asm volatile("ldmatrix.sync.aligned.m8n8.x4.trans.shared.b16 {%0,%1,%2,%3}, [%4];"
                 : "=r"(r[0]), "=r"(r[1]), "=r"(r[2]), "=r"(r[3]) : "r"(addr));
}

__device__ __forceinline__ void mma16816(float (&c)[4], const uint32_t (&a)[4],
                                         uint32_t b0, uint32_t b1) {
    asm volatile(
        "mma.sync.aligned.m16n8k16.row.col.f32.f16.f16.f32 "
        "{%0,%1,%2,%3}, {%4,%5,%6,%7}, {%8,%9}, {%0,%1,%2,%3};"
        : "+f"(c[0]), "+f"(c[1]), "+f"(c[2]), "+f"(c[3])
        : "r"(a[0]), "r"(a[1]), "r"(a[2]), "r"(a[3]), "r"(b0), "r"(b1));
}

__device__ __forceinline__ uint32_t pack_h2(__half x, __half y) {
    __half2 h = __halves2half2(x, y);
    return *(uint32_t*)&h;
}

// ---------------- bias concat -------------------------------------------------
__global__ __launch_bounds__(256) void biascat_kernel(
    const float* __restrict__ bq, const float* __restrict__ bk,
    const float* __restrict__ bv, float* __restrict__ bqkv)
{
    int i = blockIdx.x * 256 + threadIdx.x;   // 0..3071
    const float* src = (i < DD) ? bq : (i < 2 * DD) ? bk : bv;
    bqkv[i] = src[i & (DD - 1)];
}

// ---------------- fp32 -> (fp16 hi, fp16 lo) split ---------------------------
struct __align__(8) half4 { __half a, b, c, d; };

__global__ __launch_bounds__(256) void split_fp16(
    const float* __restrict__ X, __half* __restrict__ Xh,
    __half* __restrict__ Xl, int n4)
{
    int i = blockIdx.x * 256 + threadIdx.x;
    if (i >= n4) return;
    float4 v = ((const float4*)X)[i];
    __half h0 = __float2half_rn(v.x);
    __half h1 = __float2half_rn(v.y);
    __half h2 = __float2half_rn(v.z);
    __half h3 = __float2half_rn(v.w);
    half4 hv = {h0, h1, h2, h3};
    half4 lv = {__float2half_rn(v.x - __half2float(h0)),
                __float2half_rn(v.y - __half2float(h1)),
                __float2half_rn(v.z - __half2float(h2)),
                __float2half_rn(v.w - __half2float(h3))};
    ((half4*)Xh)[i] = hv;
    ((half4*)Xl)[i] = lv;
}

__global__ __launch_bounds__(256) void round_fp16(
    const float* __restrict__ X, __half* __restrict__ Xh, int n4)
{
    int i = blockIdx.x * 256 + threadIdx.x;
    if (i >= n4) return;
    float4 v = ((const float4*)X)[i];
    half4 hv = {__float2half_rn(v.x), __float2half_rn(v.y),
                __float2half_rn(v.z), __float2half_rn(v.w)};
    ((half4*)Xh)[i] = hv;
}

// ---------------- transpose + split: (Mh+Ml)[NBL][DD] -> T[DD][NBL] ----------
__global__ __launch_bounds__(256) void transpose_split_fp16(
    const __half* __restrict__ Msh, const __half* __restrict__ Msl,
    __half* __restrict__ Th, __half* __restrict__ Tl)
{
    __shared__ float tile[32][33];
    int bx = blockIdx.x;
    int by = blockIdx.y;
    int tx = threadIdx.x;
    int ty = threadIdx.y;
#pragma unroll
    for (int j = 0; j < 32; j += 8) {
        size_t off = (size_t)(by * 32 + ty + j) * DD + bx * 32 + tx;
        tile[ty + j][tx] = __half2float(Msh[off]) + __half2float(Msl[off]);
    }
    __syncthreads();
#pragma unroll
    for (int j = 0; j < 32; j += 8) {
        float v = tile[tx][ty + j];
        __half h = __float2half_rn(v);
        __half l = __float2half_rn(v - __half2float(h));
        size_t off = (size_t)(bx * 32 + ty + j) * NBL + by * 32 + tx;
        Th[off] = h;
        Tl[off] = l;
    }
}

// ---------------- mma.sync GEMM (2-pass fp16 split, 3-stage pipeline) --------
// C = (Ah+Al) @ Bh^T (+bias). fp32 out OR fp16 h/l out (Ch/Cl, cols<qcols
// scaled by qscale before splitting).
#define GPITCH 144              // bytes per smem row (64 fp16 + pad)
#define GTILE  (128 * GPITCH)   // 18432 B
#define GBUF   (2 * GTILE)      // 36864 B per stage
#define GSMEM  (3 * GBUF)       // 110592 B

__global__ __launch_bounds__(256) void gemm2(
    const __half* __restrict__ Ah, const __half* __restrict__ Al,
    const __half* __restrict__ Bh, const float* __restrict__ bias,
    float* __restrict__ C, float* __restrict__ Cpart,
    __half* __restrict__ Ch, __half* __restrict__ Cl,
    float qscale, int qcols,
    int lda, int Ksl, int N)
{
    extern __shared__ __align__(16) char smem[];
    const uint32_t sbase = smem_u32(smem);
    const int tid = threadIdx.x;
    const int lane = tid & 31;
    const int wid = tid >> 5;
    const int wm = wid >> 2;
    const int wn = wid & 3;
    const int bx = blockIdx.x;
    const int by = blockIdx.y;
    const int split = blockIdx.z;
    const int nsplit = gridDim.z;
    const int M = gridDim.y * 128;

    const __half* pA[2] = {Ah, Al};
    const int Kc = Ksl >> 6;
    const int total = 2 * Kc;

    float c[4][4][4];
#pragma unroll
    for (int i = 0; i < 4; i++)
#pragma unroll
        for (int j = 0; j < 4; j++)
#pragma unroll
            for (int f = 0; f < 4; f++) c[i][j][f] = 0.0f;

    auto load_chunk = [&](int g, int buf) {
        int p = (g >= Kc) ? 1 : 0;
        int kk = g - p * Kc;
        const __half* Abase = pA[p] + (size_t)by * 128 * lda + split * Ksl + kk * 64;
        const __half* Bbase = Bh + (size_t)bx * 128 * lda + split * Ksl + kk * 64;
        uint32_t aS = sbase + buf * GBUF;
        uint32_t bS = aS + GTILE;
#pragma unroll
        for (int j = 0; j < 4; j++) {
            int lin = tid + j * 256;
            int row = lin >> 3;
            int seg = lin & 7;
            cp_async16(aS + row * GPITCH + seg * 16,
                       Abase + (size_t)row * lda + seg * 8);
            cp_async16(bS + row * GPITCH + seg * 16,
                       Bbase + (size_t)row * lda + seg * 8);
        }
        cp_commit();
    };

    load_chunk(0, 0);
    load_chunk(1, 1);

    int buf = 0;
    for (int g = 0; g < total; g++) {
        if (g == total - 1) cp_wait<0>(); else cp_wait<1>();
        __syncthreads();
        if (g + 2 < total) {
            int nb = buf + 2; if (nb >= 3) nb -= 3;
            load_chunk(g + 2, nb);
        }

        const uint32_t aS = sbase + buf * GBUF;
        const uint32_t bS = aS + GTILE;
#pragma unroll
        for (int s = 0; s < 4; s++) {
            uint32_t a[4][4];
#pragma unroll
            for (int i = 0; i < 4; i++) {
                int row = wm * 64 + i * 16 + (lane & 15);
                ldm_x4(a[i], aS + row * GPITCH + s * 32 + ((lane >> 4) * 16));
            }
            uint32_t b[2][4];
#pragma unroll
            for (int j = 0; j < 2; j++) {
                int row = wn * 32 + j * 16 + ((lane >> 4) << 3) + (lane & 7);
                int off = ((lane >> 3) & 1) * 16;
                ldm_x4(b[j], bS + row * GPITCH + s * 32 + off);
            }
#pragma unroll
            for (int i = 0; i < 4; i++) {
#pragma unroll
                for (int j = 0; j < 2; j++) {
                    mma16816(c[i][2 * j], a[i], b[j][0], b[j][1]);
                    mma16816(c[i][2 * j + 1], a[i], b[j][2], b[j][3]);
                }
            }
        }
        if (++buf == 3) buf = 0;
    }

    const bool addb = (bias != nullptr) && (nsplit == 1);
#pragma unroll
    for (int i = 0; i < 4; i++) {
        int r0 = by * 128 + wm * 64 + i * 16 + (lane >> 2);
#pragma unroll
        for (int nt = 0; nt < 4; nt++) {
            int col = bx * 128 + wn * 32 + nt * 8 + (lane & 3) * 2;
            float bx0 = 0.0f, bx1 = 0.0f;
            if (addb) { bx0 = bias[col]; bx1 = bias[col + 1]; }
            float a0 = c[i][nt][0] + bx0, a1 = c[i][nt][1] + bx1;
            float a2 = c[i][nt][2] + bx0, a3 = c[i][nt][3] + bx1;
            if (Ch) {
                float sc = (col < qcols) ? qscale : 1.0f;
                a0 *= sc; a1 *= sc; a2 *= sc; a3 *= sc;
                __half h0 = __float2half_rn(a0), h1 = __float2half_rn(a1);
                __half h2 = __float2half_rn(a2), h3 = __float2half_rn(a3);
                *(__half2*)(Ch + (size_t)r0 * N + col) = __halves2half2(h0, h1);
                *(__half2*)(Ch + (size_t)(r0 + 8) * N + col) = __halves2half2(h2, h3);
                *(__half2*)(Cl + (size_t)r0 * N + col) =
                    __halves2half2(__float2half_rn(a0 - __half2float(h0)),
                                   __float2half_rn(a1 - __half2float(h1)));
                *(__half2*)(Cl + (size_t)(r0 + 8) * N + col) =
                    __halves2half2(__float2half_rn(a2 - __half2float(h2)),
                                   __float2half_rn(a3 - __half2float(h3)));
            } else {
                float* dst = (nsplit == 1) ? C : (Cpart + (size_t)split * M * N);
                float2 v0 = {a0, a1}, v1 = {a2, a3};
                *(float2*)(dst + (size_t)r0 * N + col) = v0;
                *(float2*)(dst + (size_t)(r0 + 8) * N + col) = v1;
            }
        }
    }
}

// ---------------- split-K reduce ---------------------------------------------
__global__ __launch_bounds__(256) void reduce_parts(
    const float* __restrict__ parts, int nparts,
    const float* __restrict__ bias, float* __restrict__ out,
    int MN, int N)
{
    int i = blockIdx.x * 256 + threadIdx.x;
    if (i >= MN / 4) return;
    float4 s = ((const float4*)parts)[i];
    for (int p = 1; p < nparts; p++) {
        float4 v = ((const float4*)(parts + (size_t)p * MN))[i];
        s.x += v.x; s.y += v.y; s.z += v.z; s.w += v.w;
    }
    if (bias) {
        int col = (i * 4) % N;
        float4 bv = *(const float4*)(bias + col);
        s.x += bv.x; s.y += bv.y; s.z += bv.z; s.w += bv.w;
    }
    ((float4*)out)[i] = s;
}

// ---------------- Attention: flash + mma.sync, fp16 inputs, cp.async ring ----
// S = Qh*Kh + Ql*Kh + Qh*Kl (1/8 already folded into Q splits by gemm2)
// O = Ph*Vh + Pl*Vh
#define AP 72                   // fp16 pitch (elements)
#define APB 144                 // bytes
#define KTB (64 * APB)          // 9216 B per tile
#define ASTG (3 * KTB)          // Kh,Kl,Vh per stage: 27648 B
#define ASMEM (3 * ASTG)        // 3 stages: 82944 B

__global__ __launch_bounds__(256) void attn_mma(
    const __half* __restrict__ QKVh, const __half* __restrict__ QKVl,
    __half* __restrict__ Oh, __half* __restrict__ Ol)
{
    extern __shared__ __align__(16) char smem[];
    const uint32_t sbase = smem_u32(smem);

    const int tid = threadIdx.x;
    const int lane = tid & 31;
    const int w = tid >> 5;
    const int q0 = blockIdx.x * 128;
    const int h = blockIdx.y;
    const int b = blockIdx.z;

    // Q fragments (already scaled by 1/8 in gemm epilogue)
    uint32_t Qah[4][4], Qal[4][4];
    {
        int r0 = b * LL + q0 + w * 16 + (lane >> 2);
        int cb = h * DK + (lane & 3) * 2;
#pragma unroll
        for (int s = 0; s < 4; s++)
#pragma unroll
            for (int t = 0; t < 4; t++) {
                size_t off = (size_t)(r0 + (t & 1) * 8) * RS3 + cb + s * 16 + (t >> 1) * 8;
                Qah[s][t] = *(const uint32_t*)(QKVh + off);
                Qal[s][t] = *(const uint32_t*)(QKVl + off);
            }
    }

    auto load_tile = [&](int kt, int stg) {
        uint32_t sb = sbase + stg * ASTG;
#pragma unroll
        for (int it = 0; it < 2; it++) {
            int lin = tid + it * 256;        // 0..511
            int row = lin >> 3;              // 0..63
            int seg = lin & 7;               // 16B segment (64 halves/row)
            size_t goff = (size_t)(b * LL + kt + row) * RS3 + DD + h * DK + seg * 8;
            cp_async16(sb + row * APB + seg * 16, QKVh + goff);              // Kh
            cp_async16(sb + KTB + row * APB + seg * 16, QKVl + goff);        // Kl
            cp_async16(sb + 2 * KTB + row * APB + seg * 16, QKVh + goff + DD); // Vh
        }
        cp_commit();
    };

    float m0 = -1e30f, m1 = -1e30f, l0 = 0.0f, l1 = 0.0f;
    float co[8][4];
#pragma unroll
    for (int j = 0; j < 8; j++)
#pragma unroll
        for (int f = 0; f < 4; f++) co[j][f] = 0.0f;

    load_tile(0, 0);
    load_tile(64, 1);

    int buf = 0;
    for (int g = 0; g < 16; g++) {
        if (g == 15) cp_wait<0>(); else cp_wait<1>();
        __syncthreads();
        if (g + 2 < 16) {
            int nb = buf + 2; if (nb >= 3) nb -= 3;
            load_tile((g + 2) * 64, nb);
        }
        const uint32_t khs = sbase + buf * ASTG;
        const uint32_t kls = khs + KTB;
        const uint32_t vhs = khs + 2 * KTB;

        // ---- QK ----
        float sc[8][4];
#pragma unroll
        for (int j = 0; j < 8; j++)
#pragma unroll
            for (int f = 0; f < 4; f++) sc[j][f] = 0.0f;

#pragma unroll
        for (int s = 0; s < 4; s++) {
#pragma unroll
            for (int j = 0; j < 4; j++) {
                uint32_t roff = (j * 16 + ((lane >> 4) << 3) + (lane & 7)) * APB
                              + s * 32 + ((lane >> 3) & 1) * 16;
                uint32_t bh[4], bl[4];
                ldm_x4(bh, khs + roff);
                ldm_x4(bl, kls + roff);
                mma16816(sc[2 * j],     Qah[s], bh[0], bh[1]);
                mma16816(sc[2 * j + 1], Qah[s], bh[2], bh[3]);
                mma16816(sc[2 * j],     Qal[s], bh[0], bh[1]);
                mma16816(sc[2 * j + 1], Qal[s], bh[2], bh[3]);
                mma16816(sc[2 * j],     Qah[s], bl[0], bl[1]);
                mma16816(sc[2 * j + 1], Qah[s], bl[2], bl[3]);
            }
        }

        // ---- online softmax ----
        float t0 = -1e30f, t1 = -1e30f;
#pragma unroll
        for (int j = 0; j < 8; j++) {
            t0 = fmaxf(t0, fmaxf(sc[j][0], sc[j][1]));
            t1 = fmaxf(t1, fmaxf(sc[j][2], sc[j][3]));
        }
        t0 = fmaxf(t0, __shfl_xor_sync(0xffffffffu, t0, 1));
        t0 = fmaxf(t0, __shfl_xor_sync(0xffffffffu, t0, 2));
        t1 = fmaxf(t1, __shfl_xor_sync(0xffffffffu, t1, 1));
        t1 = fmaxf(t1, __shfl_xor_sync(0xffffffffu, t1, 2));
        float mn0 = fmaxf(m0, t0), mn1 = fmaxf(m1, t1);
        float f0 = __expf(m0 - mn0), f1 = __expf(m1 - mn1);
        float rs0 = 0.0f, rs1 = 0.0f;
#pragma unroll
        for (int j = 0; j < 8; j++) {
            sc[j][0] = __expf(sc[j][0] - mn0);
            sc[j][1] = __expf(sc[j][1] - mn0);
            sc[j][2] = __expf(sc[j][2] - mn1);
            sc[j][3] = __expf(sc[j][3] - mn1);
            rs0 += sc[j][0] + sc[j][1];
            rs1 += sc[j][2] + sc[j][3];
        }
        rs0 += __shfl_xor_sync(0xffffffffu, rs0, 1);
        rs0 += __shfl_xor_sync(0xffffffffu, rs0, 2);
        rs1 += __shfl_xor_sync(0xffffffffu, rs1, 1);
        rs1 += __shfl_xor_sync(0xffffffffu, rs1, 2);
        l0 = l0 * f0 + rs0;
        l1 = l1 * f1 + rs1;
        m0 = mn0; m1 = mn1;
#pragma unroll
        for (int j = 0; j < 8; j++) {
            co[j][0] *= f0; co[j][1] *= f0;
            co[j][2] *= f1; co[j][3] *= f1;
        }

        // ---- PV ----
#pragma unroll
        for (int s = 0; s < 4; s++) {
            uint32_t pah[4], pal[4];
#pragma unroll
            for (int t = 0; t < 4; t++) {
                int bk = 2 * s + (t >> 1);
                float p0 = sc[bk][(t & 1) * 2];
                float p1 = sc[bk][(t & 1) * 2 + 1];
                __half h0 = __float2half_rn(p0), h1 = __float2half_rn(p1);
                pah[t] = pack_h2(h0, h1);
                pal[t] = pack_h2(__float2half_rn(p0 - __half2float(h0)),
                                 __float2half_rn(p1 - __half2float(h1)));
            }
#pragma unroll
            for (int j = 0; j < 4; j++) {
                uint32_t roff = (s * 16 + ((lane >> 3) & 1) * 8 + (lane & 7)) * APB
                              + (j * 16 + ((lane >> 4) & 1) * 8) * 2;
                uint32_t vbh[4];
                ldm_x4_trans(vbh, vhs + roff);
                mma16816(co[2 * j],     pah, vbh[0], vbh[1]);
                mma16816(co[2 * j + 1], pah, vbh[2], vbh[3]);
                mma16816(co[2 * j],     pal, vbh[0], vbh[1]);
                mma16816(co[2 * j + 1], pal, vbh[2], vbh[3]);
            }
        }
        if (++buf == 3) buf = 0;
    }

    // epilogue: normalize, write fp16 h/l merged outputs
    float inv0 = 1.0f / l0, inv1 = 1.0f / l1;
    int grow = q0 + w * 16 + (lane >> 2);
    size_t base0 = (size_t)(b * LL + grow) * DD + h * DK;
    size_t base1 = base0 + (size_t)8 * DD;
#pragma unroll
    for (int j = 0; j < 8; j++) {
        int col = j * 8 + (lane & 3) * 2;
        float a0 = co[j][0] * inv0, a1 = co[j][1] * inv0;
        float a2 = co[j][2] * inv1, a3 = co[j][3] * inv1;
        __half h0 = __float2half_rn(a0), h1 = __float2half_rn(a1);
        __half h2 = __float2half_rn(a2), h3 = __float2half_rn(a3);
        *(__half2*)(Oh + base0 + col) = __halves2half2(h0, h1);
        *(__half2*)(Oh + base1 + col) = __halves2half2(h2, h3);
        *(__half2*)(Ol + base0 + col) =
            __halves2half2(__float2half_rn(a0 - __half2float(h0)),
                           __float2half_rn(a1 - __half2float(h1)));
        *(__half2*)(Ol + base1 + col) =
            __halves2half2(__float2half_rn(a2 - __half2float(h2)),
                           __float2half_rn(a3 - __half2float(h3)));
    }
}

// ---------------- column means (two-stage, from fp16 h/l) ---------------------
__global__ __launch_bounds__(256) void colmean_part(
    const __half* __restrict__ Msh, const __half* __restrict__ Msl,
    float* __restrict__ part)
{
    int col = blockIdx.x * 256 + threadIdx.x;
    int seg = blockIdx.y;
    float s = 0.0f;
    size_t base = (size_t)seg * 256 * DD + col;
#pragma unroll 4
    for (int r = 0; r < 256; r++) {
        size_t o = base + (size_t)r * DD;
        s += __half2float(Msh[o]) + __half2float(Msl[o]);
    }
    part[seg * DD + col] = s;
}

__global__ __launch_bounds__(256) void colmean_fin(
    const float* __restrict__ part, float* __restrict__ mean)
{
    int col = blockIdx.x * 256 + threadIdx.x;
    float s = 0.0f;
#pragma unroll
    for (int seg = 0; seg < 16; seg++) s += part[seg * DD + col];
    mean[col] = s * (1.0f / (float)NBL);
}

// ---------------- DeCov partial sums (deterministic) -------------------------
__global__ void decov_row(const float* __restrict__ G,
                          const float* __restrict__ mean,
                          float* __restrict__ partial)
{
    __shared__ float red[256];
    const int i = blockIdx.x;
    const float mi = mean[i];
    const float invN = 1.0f / (float)NBL;
    float s = 0.0f;
    for (int j = threadIdx.x; j < DD; j += 256) {
        if (j == i) continue;
        float c = G[(size_t)i * DD + j] * invN - mi * mean[j];
        s += c * c;
    }
    red[threadIdx.x] = s;
    __syncthreads();
    for (int off = 128; off > 0; off >>= 1) {
        if (threadIdx.x < off) red[threadIdx.x] += red[threadIdx.x + off];
        __syncthreads();
    }
    if (threadIdx.x == 0) partial[i] = red[0];
}

__global__ void decov_final(const float* __restrict__ partial, float* __restrict__ out)
{
    __shared__ float red[256];
    float s = 0.0f;
    for (int i = threadIdx.x; i < DD; i += 256) s += partial[i];
    red[threadIdx.x] = s;
    __syncthreads();
    for (int off = 128; off > 0; off >>= 1) {
        if (threadIdx.x < off) red[threadIdx.x] += red[threadIdx.x + off];
        __syncthreads();
    }
    if (threadIdx.x == 0) out[0] = 0.5f * red[0];
}

// ---------------- launch ------------------------------------------------------
extern "C" void kernel_launch(void* const* d_in, const int* in_sizes, int n_in,
                              void* d_out, int out_size)
{
    const float* x  = (const float*)d_in[0];
    const float* Wq = (const float*)d_in[1];
    const float* bq = (const float*)d_in[2];
    const float* Wk = (const float*)d_in[3];
    const float* bk = (const float*)d_in[4];
    const float* Wv = (const float*)d_in[5];
    const float* bv = (const float*)d_in[6];
    const float* Wo = (const float*)d_in[7];
    const float* bo = (const float*)d_in[8];
    float* out = (float*)d_out;

    float *Gp, *meanp, *meanpartp, *partp, *Gpart, *bqkv;
    cudaGetSymbolAddress((void**)&Gp, g_G);
    cudaGetSymbolAddress((void**)&meanp, g_mean);
    cudaGetSymbolAddress((void**)&meanpartp, g_meanpart);
    cudaGetSymbolAddress((void**)&partp, g_partial);
    cudaGetSymbolAddress((void**)&Gpart, g_Gpart);
    cudaGetSymbolAddress((void**)&bqkv, g_bqkv);

    __half *QKVh, *QKVl, *xh, *xl, *Mh, *Ml, *Mth, *Mtl, *Wqkvh, *Woh;
    cudaGetSymbolAddress((void**)&QKVh, g_QKVh);
    cudaGetSymbolAddress((void**)&QKVl, g_QKVl);
    cudaGetSymbolAddress((void**)&xh, g_xh);
    cudaGetSymbolAddress((void**)&xl, g_xl);
    cudaGetSymbolAddress((void**)&Mh, g_Mh);
    cudaGetSymbolAddress((void**)&Ml, g_Ml);
    cudaGetSymbolAddress((void**)&Mth, g_Mth);
    cudaGetSymbolAddress((void**)&Mtl, g_Mtl);
    cudaGetSymbolAddress((void**)&Wqkvh, g_Wqkvh);
    cudaGetSymbolAddress((void**)&Woh, g_Woh);

    cudaFuncSetAttribute(gemm2, cudaFuncAttributeMaxDynamicSharedMemorySize,
                         GSMEM);
    cudaFuncSetAttribute(attn_mma, cudaFuncAttributeMaxDynamicSharedMemorySize,
                         ASMEM);

    const int n4x = MTOT * DD / 4;
    const int n4w = DD * DD / 4;

    biascat_kernel<<<12, 256>>>(bq, bk, bv, bqkv);
    split_fp16<<<n4x / 256, 256>>>(x, xh, xl, n4x);
    round_fp16<<<n4w / 256, 256>>>(Wq, Wqkvh, n4w);
    round_fp16<<<n4w / 256, 256>>>(Wk, Wqkvh + DD * DD, n4w);
    round_fp16<<<n4w / 256, 256>>>(Wv, Wqkvh + 2 * DD * DD, n4w);
    round_fp16<<<n4w / 256, 256>>>(Wo, Woh, n4w);

    // fused QKV projection -> fp16 h/l, Q columns pre-scaled by 1/8
    dim3 gQKV(RS3 / 128, MTOT / 128, 1);       // (24, 32)
    gemm2<<<gQKV, 256, GSMEM>>>(xh, xl, Wqkvh, bqkv, nullptr, nullptr,
                                QKVh, QKVl, 0.125f, DD, DD, DD, RS3);

    // attention (tensor-core flash on fp16 splits; writes Mh/Ml)
    dim3 gAttn(LL / 128, HH, BB);              // (8, 16, 4)
    attn_mma<<<gAttn, 256, ASMEM>>>(QKVh, QKVl, Mh, Ml);

    // transposed split of M for SYRK
    transpose_split_fp16<<<dim3(DD / 32, NBL / 32), dim3(32, 8)>>>(Mh, Ml, Mth, Mtl);

    // output projection (fp32 out + bias)
    dim3 gOut(DD / 128, MTOT / 128, 1);        // (8, 32)
    gemm2<<<gOut, 256, GSMEM>>>(Mh, Ml, Woh, bo, out, nullptr,
                                nullptr, nullptr, 1.0f, 0, DD, DD, DD);

    // DeCov path
    colmean_part<<<dim3(4, 16), 256>>>(Mh, Ml, meanpartp);
    colmean_fin<<<4, 256>>>(meanpartp, meanp);
    dim3 gSyrk(DD / 128, DD / 128, 4);         // (8, 8, 4)
    gemm2<<<gSyrk, 256, GSMEM>>>(Mth, Mtl, Mth, nullptr, nullptr, Gpart,
                                 nullptr, nullptr, 1.0f, 0, NBL, NBL / 4, DD);
    reduce_parts<<<(DD * DD / 4) / 256, 256>>>(Gpart, 4, nullptr, Gp,
                                               DD * DD, DD);
    decov_row<<<DD, 256>>>(Gp, meanp, partp);
    decov_final<<<1, 256>>>(partp, out + (out_size - 1));
}

// round 8
// speedup vs baseline: 2.7774x; 1.1039x over previous
#include <cuda_runtime.h>
#include <cuda_fp16.h>
#include <math.h>
#include <stdint.h>

// Problem constants
#define BB 4
#define LL 1024
#define DD 1024
#define HH 16
#define DK 64
#define MTOT (BB * LL)          // 4096
#define NBL  (BB * LL)          // 4096
#define RS3  (3 * DD)           // 3072

// ---------------- scratch (static device memory; no allocations) -------------
__device__ float g_G[DD * DD];
__device__ float g_mean[DD];
__device__ float g_meanpart[16 * DD];
__device__ float g_partial[DD];
__device__ float g_Gpart[4 * DD * DD];
__device__ float g_bqkv[3 * DD];

__device__ __align__(16) __half g_QKVh[MTOT * RS3];
__device__ __align__(16) __half g_QKVl[MTOT * RS3];
__device__ __align__(16) __half g_xh[MTOT * DD];
__device__ __align__(16) __half g_xl[MTOT * DD];
__device__ __align__(16) __half g_Mh[MTOT * DD];
__device__ __align__(16) __half g_Ml[MTOT * DD];
__device__ __align__(16) __half g_Mth[DD * NBL];
__device__ __align__(16) __half g_Mtl[DD * NBL];
__device__ __align__(16) __half g_Wqkvh[3 * DD * DD];
__device__ __align__(16) __half g_Woh[DD * DD];

// ---------------- small PTX helpers ------------------------------------------
__device__ __forceinline__ uint32_t smem_u32(const void* p) {
    uint32_t a;
    asm("{ .reg .u64 t; cvta.to.shared.u64 t, %1; cvt.u32.u64 %0, t; }"
        : "=r"(a) : "l"(p));
    return a;
}

__device__ __forceinline__ void cp_async16(uint32_t saddr, const void* gptr) {
    asm volatile("cp.async.ca.shared.global [%0], [%1], 16;"
                 :: "r"(saddr), "l"(gptr));
}
__device__ __forceinline__ void cp_commit() {
    asm volatile("cp.async.commit_group;" ::: "memory");
}
template <int N>
__device__ __forceinline__ void cp_wait() {
    asm volatile("cp.async.wait_group %0;" :: "n"(N) : "memory");
}

__device__ __forceinline__ void ldm_x4(uint32_t (&r)[4], uint32_t addr) {
    asm volatile("ldmatrix.sync.aligned.m8n8.x4.shared.b16 {%0,%1,%2,%3}, [%4];"
                 : "=r"(r[0]), "=r"(r[1]), "=r"(r[2]), "=r"(r[3]) : "r"(addr));
}
__device__ __forceinline__ void ldm_x4_trans(uint32_t (&r)[4], uint32_t addr) {
    asm volatile("ldmatrix.sync.aligned.m8n8.x4.trans.shared.b16 {%0,%1,%2,%3}, [%4];"
                 : "=r"(r[0]), "=r"(r[1]), "=r"(r[2]), "=r"(r[3]) : "r"(addr));
}

__device__ __forceinline__ void mma16816(float (&c)[4], const uint32_t (&a)[4],
                                         uint32_t b0, uint32_t b1) {
    asm volatile(
        "mma.sync.aligned.m16n8k16.row.col.f32.f16.f16.f32 "
        "{%0,%1,%2,%3}, {%4,%5,%6,%7}, {%8,%9}, {%0,%1,%2,%3};"
        : "+f"(c[0]), "+f"(c[1]), "+f"(c[2]), "+f"(c[3])
        : "r"(a[0]), "r"(a[1]), "r"(a[2]), "r"(a[3]), "r"(b0), "r"(b1));
}

__device__ __forceinline__ uint32_t pack_h2(__half x, __half y) {
    __half2 h = __halves2half2(x, y);
    return *(uint32_t*)&h;
}

struct __align__(8) half4 { __half a, b, c, d; };

// ---------------- prep mega-kernel: x split + weight rounds + bias concat ----
__global__ __launch_bounds__(256) void prep_kernel(
    const float* __restrict__ x,
    const float* __restrict__ Wq, const float* __restrict__ Wk,
    const float* __restrict__ Wv, const float* __restrict__ Wo,
    const float* __restrict__ bq, const float* __restrict__ bk,
    const float* __restrict__ bv,
    __half* __restrict__ xh, __half* __restrict__ xl,
    __half* __restrict__ Wqkvh, __half* __restrict__ Woh,
    float* __restrict__ bqkv)
{
    int t = blockIdx.x;
    int tid = threadIdx.x;
    if (t < 4096) {
        // x split: 1M float4
        int i = t * 256 + tid;
        float4 v = ((const float4*)x)[i];
        __half h0 = __float2half_rn(v.x);
        __half h1 = __float2half_rn(v.y);
        __half h2 = __float2half_rn(v.z);
        __half h3 = __float2half_rn(v.w);
        half4 hv = {h0, h1, h2, h3};
        half4 lv = {__float2half_rn(v.x - __half2float(h0)),
                    __float2half_rn(v.y - __half2float(h1)),
                    __float2half_rn(v.z - __half2float(h2)),
                    __float2half_rn(v.w - __half2float(h3))};
        ((half4*)xh)[i] = hv;
        ((half4*)xl)[i] = lv;
    } else if (t < 8192) {
        int wsel = (t - 4096) >> 10;          // 0..3
        int blk = (t - 4096) & 1023;
        const float* src = (wsel == 0) ? Wq : (wsel == 1) ? Wk
                         : (wsel == 2) ? Wv : Wo;
        __half* dst = (wsel < 3) ? (Wqkvh + (size_t)wsel * DD * DD) : Woh;
        int i = blk * 256 + tid;
        float4 v = ((const float4*)src)[i];
        half4 hv = {__float2half_rn(v.x), __float2half_rn(v.y),
                    __float2half_rn(v.z), __float2half_rn(v.w)};
        ((half4*)dst)[i] = hv;
    } else {
        int i = (t - 8192) * 256 + tid;       // 0..3071
        if (i < RS3) {
            const float* src = (i < DD) ? bq : (i < 2 * DD) ? bk : bv;
            bqkv[i] = src[i & (DD - 1)];
        }
    }
}

// ---------------- GEMM body (shared by gemm2 + fused_mid) --------------------
#define GPITCH 144
#define GTILE  (128 * GPITCH)
#define GBUF   (2 * GTILE)
#define GSMEM  (3 * GBUF)       // 110592 B

__device__ __forceinline__ void gemm_body(
    const __half* __restrict__ Ah, const __half* __restrict__ Al,
    const __half* __restrict__ Bh, const float* __restrict__ bias,
    float* __restrict__ C, float* __restrict__ Cpart,
    __half* __restrict__ Ch, __half* __restrict__ Cl,
    float qscale, int qcols,
    int lda, int Ksl, int N, int M,
    int bx, int by, int split, int nsplit, char* smem)
{
    const uint32_t sbase = smem_u32(smem);
    const int tid = threadIdx.x;
    const int lane = tid & 31;
    const int wid = tid >> 5;
    const int wm = wid >> 2;
    const int wn = wid & 3;

    const __half* pA[2] = {Ah, Al};
    const int Kc = Ksl >> 6;
    const int total = 2 * Kc;

    float c[4][4][4];
#pragma unroll
    for (int i = 0; i < 4; i++)
#pragma unroll
        for (int j = 0; j < 4; j++)
#pragma unroll
            for (int f = 0; f < 4; f++) c[i][j][f] = 0.0f;

    auto load_chunk = [&](int g, int buf) {
        int p = (g >= Kc) ? 1 : 0;
        int kk = g - p * Kc;
        const __half* Abase = pA[p] + (size_t)by * 128 * lda + split * Ksl + kk * 64;
        const __half* Bbase = Bh + (size_t)bx * 128 * lda + split * Ksl + kk * 64;
        uint32_t aS = sbase + buf * GBUF;
        uint32_t bS = aS + GTILE;
#pragma unroll
        for (int j = 0; j < 4; j++) {
            int lin = tid + j * 256;
            int row = lin >> 3;
            int seg = lin & 7;
            cp_async16(aS + row * GPITCH + seg * 16,
                       Abase + (size_t)row * lda + seg * 8);
            cp_async16(bS + row * GPITCH + seg * 16,
                       Bbase + (size_t)row * lda + seg * 8);
        }
        cp_commit();
    };

    load_chunk(0, 0);
    load_chunk(1, 1);

    int buf = 0;
    for (int g = 0; g < total; g++) {
        if (g == total - 1) cp_wait<0>(); else cp_wait<1>();
        __syncthreads();
        if (g + 2 < total) {
            int nb = buf + 2; if (nb >= 3) nb -= 3;
            load_chunk(g + 2, nb);
        }

        const uint32_t aS = sbase + buf * GBUF;
        const uint32_t bS = aS + GTILE;
#pragma unroll
        for (int s = 0; s < 4; s++) {
            uint32_t a[4][4];
#pragma unroll
            for (int i = 0; i < 4; i++) {
                int row = wm * 64 + i * 16 + (lane & 15);
                ldm_x4(a[i], aS + row * GPITCH + s * 32 + ((lane >> 4) * 16));
            }
            uint32_t b[2][4];
#pragma unroll
            for (int j = 0; j < 2; j++) {
                int row = wn * 32 + j * 16 + ((lane >> 4) << 3) + (lane & 7);
                int off = ((lane >> 3) & 1) * 16;
                ldm_x4(b[j], bS + row * GPITCH + s * 32 + off);
            }
#pragma unroll
            for (int i = 0; i < 4; i++) {
#pragma unroll
                for (int j = 0; j < 2; j++) {
                    mma16816(c[i][2 * j], a[i], b[j][0], b[j][1]);
                    mma16816(c[i][2 * j + 1], a[i], b[j][2], b[j][3]);
                }
            }
        }
        if (++buf == 3) buf = 0;
    }

    const bool addb = (bias != nullptr) && (nsplit == 1);
#pragma unroll
    for (int i = 0; i < 4; i++) {
        int r0 = by * 128 + wm * 64 + i * 16 + (lane >> 2);
#pragma unroll
        for (int nt = 0; nt < 4; nt++) {
            int col = bx * 128 + wn * 32 + nt * 8 + (lane & 3) * 2;
            float bx0 = 0.0f, bx1 = 0.0f;
            if (addb) { bx0 = bias[col]; bx1 = bias[col + 1]; }
            float a0 = c[i][nt][0] + bx0, a1 = c[i][nt][1] + bx1;
            float a2 = c[i][nt][2] + bx0, a3 = c[i][nt][3] + bx1;
            if (Ch) {
                float sc = (col < qcols) ? qscale : 1.0f;
                a0 *= sc; a1 *= sc; a2 *= sc; a3 *= sc;
                __half h0 = __float2half_rn(a0), h1 = __float2half_rn(a1);
                __half h2 = __float2half_rn(a2), h3 = __float2half_rn(a3);
                *(__half2*)(Ch + (size_t)r0 * N + col) = __halves2half2(h0, h1);
                *(__half2*)(Ch + (size_t)(r0 + 8) * N + col) = __halves2half2(h2, h3);
                *(__half2*)(Cl + (size_t)r0 * N + col) =
                    __halves2half2(__float2half_rn(a0 - __half2float(h0)),
                                   __float2half_rn(a1 - __half2float(h1)));
                *(__half2*)(Cl + (size_t)(r0 + 8) * N + col) =
                    __halves2half2(__float2half_rn(a2 - __half2float(h2)),
                                   __float2half_rn(a3 - __half2float(h3)));
            } else {
                float* dst = (nsplit == 1) ? C : (Cpart + (size_t)split * M * N);
                float2 v0 = {a0, a1}, v1 = {a2, a3};
                *(float2*)(dst + (size_t)r0 * N + col) = v0;
                *(float2*)(dst + (size_t)(r0 + 8) * N + col) = v1;
            }
        }
    }
}

// ---------------- QKV GEMM kernel --------------------------------------------
__global__ __launch_bounds__(256, 2) void gemm2(
    const __half* __restrict__ Ah, const __half* __restrict__ Al,
    const __half* __restrict__ Bh, const float* __restrict__ bias,
    __half* __restrict__ Ch, __half* __restrict__ Cl,
    float qscale, int qcols, int lda, int Ksl, int N)
{
    extern __shared__ __align__(16) char smem[];
    gemm_body(Ah, Al, Bh, bias, nullptr, nullptr, Ch, Cl, qscale, qcols,
              lda, Ksl, N, gridDim.y * 128,
              blockIdx.x, blockIdx.y, 0, 1, smem);
}

// ---------------- fused mid: out-proj GEMM + SYRK + colmean-part -------------
__global__ __launch_bounds__(256, 2) void fused_mid(
    const __half* __restrict__ Mh, const __half* __restrict__ Ml,
    const __half* __restrict__ Woh, const float* __restrict__ bo,
    float* __restrict__ out,
    const __half* __restrict__ Mth, const __half* __restrict__ Mtl,
    float* __restrict__ Gpart, float* __restrict__ meanpart)
{
    extern __shared__ __align__(16) char smem[];
    int t = blockIdx.x;
    if (t < 256) {
        // out projection: [4096,1024] = M @ Wo^T + bo
        gemm_body(Mh, Ml, Woh, bo, out, nullptr, nullptr, nullptr, 1.0f, 0,
                  DD, DD, DD, MTOT, t & 7, t >> 3, 0, 1, smem);
    } else if (t < 512) {
        // SYRK split-K=4: Gpart[s] = Mt_slice @ Mt^T
        int s = t - 256;
        gemm_body(Mth, Mtl, Mth, nullptr, nullptr, Gpart, nullptr, nullptr,
                  1.0f, 0, NBL, NBL / 4, DD, DD,
                  s & 7, (s >> 3) & 7, s >> 6, 4, smem);
    } else {
        // colmean partials: 64 blocks -> part[16][DD]
        int idx = t - 512;
        int col = (idx & 3) * 256 + threadIdx.x;
        int seg = idx >> 2;
        float s = 0.0f;
        size_t base = (size_t)seg * 256 * DD + col;
#pragma unroll 4
        for (int r = 0; r < 256; r++) {
            size_t o = base + (size_t)r * DD;
            s += __half2float(Mh[o]) + __half2float(Ml[o]);
        }
        meanpart[seg * DD + col] = s;
    }
}

// ---------------- fused fin: split-K reduce + colmean finalize ---------------
__global__ __launch_bounds__(256) void fused_fin(
    const float* __restrict__ Gpart, float* __restrict__ G,
    const float* __restrict__ meanpart, float* __restrict__ mean)
{
    int t = blockIdx.x;
    if (t < 1024) {
        int i = t * 256 + threadIdx.x;        // float4 idx over DD*DD/4
        float4 s = ((const float4*)Gpart)[i];
#pragma unroll
        for (int p = 1; p < 4; p++) {
            float4 v = ((const float4*)(Gpart + (size_t)p * DD * DD))[i];
            s.x += v.x; s.y += v.y; s.z += v.z; s.w += v.w;
        }
        ((float4*)G)[i] = s;
    } else {
        int col = (t - 1024) * 256 + threadIdx.x;
        float s = 0.0f;
#pragma unroll
        for (int seg = 0; seg < 16; seg++) s += meanpart[seg * DD + col];
        mean[col] = s * (1.0f / (float)NBL);
    }
}

// ---------------- Attention: flash + mma.sync, fp16 inputs, cp.async ring ----
#define AP 72
#define APB 144
#define KTB (64 * APB)
#define ASTG (3 * KTB)
#define ASMEM (3 * ASTG)        // 82944 B

__global__ __launch_bounds__(256, 2) void attn_mma(
    const __half* __restrict__ QKVh, const __half* __restrict__ QKVl,
    __half* __restrict__ Oh, __half* __restrict__ Ol)
{
    extern __shared__ __align__(16) char smem[];
    const uint32_t sbase = smem_u32(smem);

    const int tid = threadIdx.x;
    const int lane = tid & 31;
    const int w = tid >> 5;
    const int q0 = blockIdx.x * 128;
    const int h = blockIdx.y;
    const int b = blockIdx.z;

    uint32_t Qah[4][4], Qal[4][4];
    {
        int r0 = b * LL + q0 + w * 16 + (lane >> 2);
        int cb = h * DK + (lane & 3) * 2;
#pragma unroll
        for (int s = 0; s < 4; s++)
#pragma unroll
            for (int t2 = 0; t2 < 4; t2++) {
                size_t off = (size_t)(r0 + (t2 & 1) * 8) * RS3 + cb + s * 16 + (t2 >> 1) * 8;
                Qah[s][t2] = *(const uint32_t*)(QKVh + off);
                Qal[s][t2] = *(const uint32_t*)(QKVl + off);
            }
    }

    auto load_tile = [&](int kt, int stg) {
        uint32_t sb = sbase + stg * ASTG;
#pragma unroll
        for (int it = 0; it < 2; it++) {
            int lin = tid + it * 256;
            int row = lin >> 3;
            int seg = lin & 7;
            size_t goff = (size_t)(b * LL + kt + row) * RS3 + DD + h * DK + seg * 8;
            cp_async16(sb + row * APB + seg * 16, QKVh + goff);
            cp_async16(sb + KTB + row * APB + seg * 16, QKVl + goff);
            cp_async16(sb + 2 * KTB + row * APB + seg * 16, QKVh + goff + DD);
        }
        cp_commit();
    };

    float m0 = -1e30f, m1 = -1e30f, l0 = 0.0f, l1 = 0.0f;
    float co[8][4];
#pragma unroll
    for (int j = 0; j < 8; j++)
#pragma unroll
        for (int f = 0; f < 4; f++) co[j][f] = 0.0f;

    load_tile(0, 0);
    load_tile(64, 1);

    int buf = 0;
    for (int g = 0; g < 16; g++) {
        if (g == 15) cp_wait<0>(); else cp_wait<1>();
        __syncthreads();
        if (g + 2 < 16) {
            int nb = buf + 2; if (nb >= 3) nb -= 3;
            load_tile((g + 2) * 64, nb);
        }
        const uint32_t khs = sbase + buf * ASTG;
        const uint32_t kls = khs + KTB;
        const uint32_t vhs = khs + 2 * KTB;

        float sc[8][4];
#pragma unroll
        for (int j = 0; j < 8; j++)
#pragma unroll
            for (int f = 0; f < 4; f++) sc[j][f] = 0.0f;

#pragma unroll
        for (int s = 0; s < 4; s++) {
#pragma unroll
            for (int j = 0; j < 4; j++) {
                uint32_t roff = (j * 16 + ((lane >> 4) << 3) + (lane & 7)) * APB
                              + s * 32 + ((lane >> 3) & 1) * 16;
                uint32_t bh[4], bl[4];
                ldm_x4(bh, khs + roff);
                ldm_x4(bl, kls + roff);
                mma16816(sc[2 * j],     Qah[s], bh[0], bh[1]);
                mma16816(sc[2 * j + 1], Qah[s], bh[2], bh[3]);
                mma16816(sc[2 * j],     Qal[s], bh[0], bh[1]);
                mma16816(sc[2 * j + 1], Qal[s], bh[2], bh[3]);
                mma16816(sc[2 * j],     Qah[s], bl[0], bl[1]);
                mma16816(sc[2 * j + 1], Qah[s], bl[2], bl[3]);
            }
        }

        float t0 = -1e30f, t1 = -1e30f;
#pragma unroll
        for (int j = 0; j < 8; j++) {
            t0 = fmaxf(t0, fmaxf(sc[j][0], sc[j][1]));
            t1 = fmaxf(t1, fmaxf(sc[j][2], sc[j][3]));
        }
        t0 = fmaxf(t0, __shfl_xor_sync(0xffffffffu, t0, 1));
        t0 = fmaxf(t0, __shfl_xor_sync(0xffffffffu, t0, 2));
        t1 = fmaxf(t1, __shfl_xor_sync(0xffffffffu, t1, 1));
        t1 = fmaxf(t1, __shfl_xor_sync(0xffffffffu, t1, 2));
        float mn0 = fmaxf(m0, t0), mn1 = fmaxf(m1, t1);
        float f0 = __expf(m0 - mn0), f1 = __expf(m1 - mn1);
        float rs0 = 0.0f, rs1 = 0.0f;
#pragma unroll
        for (int j = 0; j < 8; j++) {
            sc[j][0] = __expf(sc[j][0] - mn0);
            sc[j][1] = __expf(sc[j][1] - mn0);
            sc[j][2] = __expf(sc[j][2] - mn1);
            sc[j][3] = __expf(sc[j][3] - mn1);
            rs0 += sc[j][0] + sc[j][1];
            rs1 += sc[j][2] + sc[j][3];
        }
        rs0 += __shfl_xor_sync(0xffffffffu, rs0, 1);
        rs0 += __shfl_xor_sync(0xffffffffu, rs0, 2);
        rs1 += __shfl_xor_sync(0xffffffffu, rs1, 1);
        rs1 += __shfl_xor_sync(0xffffffffu, rs1, 2);
        l0 = l0 * f0 + rs0;
        l1 = l1 * f1 + rs1;
        m0 = mn0; m1 = mn1;
#pragma unroll
        for (int j = 0; j < 8; j++) {
            co[j][0] *= f0; co[j][1] *= f0;
            co[j][2] *= f1; co[j][3] *= f1;
        }

#pragma unroll
        for (int s = 0; s < 4; s++) {
            uint32_t pah[4], pal[4];
#pragma unroll
            for (int t2 = 0; t2 < 4; t2++) {
                int bk = 2 * s + (t2 >> 1);
                float p0 = sc[bk][(t2 & 1) * 2];
                float p1 = sc[bk][(t2 & 1) * 2 + 1];
                __half h0 = __float2half_rn(p0), h1 = __float2half_rn(p1);
                pah[t2] = pack_h2(h0, h1);
                pal[t2] = pack_h2(__float2half_rn(p0 - __half2float(h0)),
                                  __float2half_rn(p1 - __half2float(h1)));
            }
#pragma unroll
            for (int j = 0; j < 4; j++) {
                uint32_t roff = (s * 16 + ((lane >> 3) & 1) * 8 + (lane & 7)) * APB
                              + (j * 16 + ((lane >> 4) & 1) * 8) * 2;
                uint32_t vbh[4];
                ldm_x4_trans(vbh, vhs + roff);
                mma16816(co[2 * j],     pah, vbh[0], vbh[1]);
                mma16816(co[2 * j + 1], pah, vbh[2], vbh[3]);
                mma16816(co[2 * j],     pal, vbh[0], vbh[1]);
                mma16816(co[2 * j + 1], pal, vbh[2], vbh[3]);
            }
        }
        if (++buf == 3) buf = 0;
    }

    float inv0 = 1.0f / l0, inv1 = 1.0f / l1;
    int grow = q0 + w * 16 + (lane >> 2);
    size_t base0 = (size_t)(b * LL + grow) * DD + h * DK;
    size_t base1 = base0 + (size_t)8 * DD;
#pragma unroll
    for (int j = 0; j < 8; j++) {
        int col = j * 8 + (lane & 3) * 2;
        float a0 = co[j][0] * inv0, a1 = co[j][1] * inv0;
        float a2 = co[j][2] * inv1, a3 = co[j][3] * inv1;
        __half h0 = __float2half_rn(a0), h1 = __float2half_rn(a1);
        __half h2 = __float2half_rn(a2), h3 = __float2half_rn(a3);
        *(__half2*)(Oh + base0 + col) = __halves2half2(h0, h1);
        *(__half2*)(Oh + base1 + col) = __halves2half2(h2, h3);
        *(__half2*)(Ol + base0 + col) =
            __halves2half2(__float2half_rn(a0 - __half2float(h0)),
                           __float2half_rn(a1 - __half2float(h1)));
        *(__half2*)(Ol + base1 + col) =
            __halves2half2(__float2half_rn(a2 - __half2float(h2)),
                           __float2half_rn(a3 - __half2float(h3)));
    }
}

// ---------------- transpose + split: (Mh+Ml)[NBL][DD] -> T[DD][NBL] ----------
__global__ __launch_bounds__(256) void transpose_split_fp16(
    const __half* __restrict__ Msh, const __half* __restrict__ Msl,
    __half* __restrict__ Th, __half* __restrict__ Tl)
{
    __shared__ float tile[32][33];
    int bx = blockIdx.x;
    int by = blockIdx.y;
    int tx = threadIdx.x;
    int ty = threadIdx.y;
#pragma unroll
    for (int j = 0; j < 32; j += 8) {
        size_t off = (size_t)(by * 32 + ty + j) * DD + bx * 32 + tx;
        tile[ty + j][tx] = __half2float(Msh[off]) + __half2float(Msl[off]);
    }
    __syncthreads();
#pragma unroll
    for (int j = 0; j < 32; j += 8) {
        float v = tile[tx][ty + j];
        __half h = __float2half_rn(v);
        __half l = __float2half_rn(v - __half2float(h));
        size_t off = (size_t)(bx * 32 + ty + j) * NBL + by * 32 + tx;
        Th[off] = h;
        Tl[off] = l;
    }
}

// ---------------- DeCov partial sums (deterministic) -------------------------
__global__ void decov_row(const float* __restrict__ G,
                          const float* __restrict__ mean,
                          float* __restrict__ partial)
{
    __shared__ float red[256];
    const int i = blockIdx.x;
    const float mi = mean[i];
    const float invN = 1.0f / (float)NBL;
    float s = 0.0f;
    for (int j = threadIdx.x; j < DD; j += 256) {
        if (j == i) continue;
        float c = G[(size_t)i * DD + j] * invN - mi * mean[j];
        s += c * c;
    }
    red[threadIdx.x] = s;
    __syncthreads();
    for (int off = 128; off > 0; off >>= 1) {
        if (threadIdx.x < off) red[threadIdx.x] += red[threadIdx.x + off];
        __syncthreads();
    }
    if (threadIdx.x == 0) partial[i] = red[0];
}

__global__ void decov_final(const float* __restrict__ partial, float* __restrict__ out)
{
    __shared__ float red[256];
    float s = 0.0f;
    for (int i = threadIdx.x; i < DD; i += 256) s += partial[i];
    red[threadIdx.x] = s;
    __syncthreads();
    for (int off = 128; off > 0; off >>= 1) {
        if (threadIdx.x < off) red[threadIdx.x] += red[threadIdx.x + off];
        __syncthreads();
    }
    if (threadIdx.x == 0) out[0] = 0.5f * red[0];
}

// ---------------- launch ------------------------------------------------------
extern "C" void kernel_launch(void* const* d_in, const int* in_sizes, int n_in,
                              void* d_out, int out_size)
{
    const float* x  = (const float*)d_in[0];
    const float* Wq = (const float*)d_in[1];
    const float* bq = (const float*)d_in[2];
    const float* Wk = (const float*)d_in[3];
    const float* bk = (const float*)d_in[4];
    const float* Wv = (const float*)d_in[5];
    const float* bv = (const float*)d_in[6];
    const float* Wo = (const float*)d_in[7];
    const float* bo = (const float*)d_in[8];
    float* out = (float*)d_out;

    float *Gp, *meanp, *meanpartp, *partp, *Gpart, *bqkv;
    cudaGetSymbolAddress((void**)&Gp, g_G);
    cudaGetSymbolAddress((void**)&meanp, g_mean);
    cudaGetSymbolAddress((void**)&meanpartp, g_meanpart);
    cudaGetSymbolAddress((void**)&partp, g_partial);
    cudaGetSymbolAddress((void**)&Gpart, g_Gpart);
    cudaGetSymbolAddress((void**)&bqkv, g_bqkv);

    __half *QKVh, *QKVl, *xh, *xl, *Mh, *Ml, *Mth, *Mtl, *Wqkvh, *Woh;
    cudaGetSymbolAddress((void**)&QKVh, g_QKVh);
    cudaGetSymbolAddress((void**)&QKVl, g_QKVl);
    cudaGetSymbolAddress((void**)&xh, g_xh);
    cudaGetSymbolAddress((void**)&xl, g_xl);
    cudaGetSymbolAddress((void**)&Mh, g_Mh);
    cudaGetSymbolAddress((void**)&Ml, g_Ml);
    cudaGetSymbolAddress((void**)&Mth, g_Mth);
    cudaGetSymbolAddress((void**)&Mtl, g_Mtl);
    cudaGetSymbolAddress((void**)&Wqkvh, g_Wqkvh);
    cudaGetSymbolAddress((void**)&Woh, g_Woh);

    cudaFuncSetAttribute(gemm2, cudaFuncAttributeMaxDynamicSharedMemorySize,
                         GSMEM);
    cudaFuncSetAttribute(fused_mid, cudaFuncAttributeMaxDynamicSharedMemorySize,
                         GSMEM);
    cudaFuncSetAttribute(attn_mma, cudaFuncAttributeMaxDynamicSharedMemorySize,
                         ASMEM);

    // 1. prep: x split + 4 weight roundings + bias concat
    prep_kernel<<<8204, 256>>>(x, Wq, Wk, Wv, Wo, bq, bk, bv,
                               xh, xl, Wqkvh, Woh, bqkv);

    // 2. fused QKV projection -> fp16 h/l, Q columns pre-scaled by 1/8
    dim3 gQKV(RS3 / 128, MTOT / 128, 1);       // (24, 32)
    gemm2<<<gQKV, 256, GSMEM>>>(xh, xl, Wqkvh, bqkv,
                                QKVh, QKVl, 0.125f, DD, DD, DD, RS3);

    // 3. attention
    dim3 gAttn(LL / 128, HH, BB);              // (8, 16, 4)
    attn_mma<<<gAttn, 256, ASMEM>>>(QKVh, QKVl, Mh, Ml);

    // 4. transposed split of M for SYRK
    transpose_split_fp16<<<dim3(DD / 32, NBL / 32), dim3(32, 8)>>>(Mh, Ml, Mth, Mtl);

    // 5. fused: out-proj GEMM (256) + SYRK split-4 (256) + colmean-part (64)
    fused_mid<<<576, 256, GSMEM>>>(Mh, Ml, Woh, bo, out,
                                   Mth, Mtl, Gpart, meanpartp);

    // 6. fused: split-K reduce (1024) + colmean finalize (4)
    fused_fin<<<1028, 256>>>(Gpart, Gp, meanpartp, meanp);

    // 7-8. DeCov reduction
    decov_row<<<DD, 256>>>(Gp, meanp, partp);
    decov_final<<<1, 256>>>(partp, out + (out_size - 1));
}

// round 9
// speedup vs baseline: 2.9298x; 1.0549x over previous
#include <cuda_runtime.h>
#include <cuda_fp16.h>
#include <math.h>
#include <stdint.h>

// Problem constants
#define BB 4
#define LL 1024
#define DD 1024
#define HH 16
#define DK 64
#define MTOT (BB * LL)          // 4096
#define NBL  (BB * LL)          // 4096
#define RS3  (3 * DD)           // 3072

// ---------------- scratch (static device memory; no allocations) -------------
__device__ float g_mean[DD];
__device__ float g_meanpart[16 * DD];
__device__ float g_partial[160];
__device__ float g_Gpart[4 * DD * DD];
__device__ float g_bqkv[3 * DD];

__device__ __align__(16) __half g_QKVh[MTOT * RS3];
__device__ __align__(16) __half g_QKVl[MTOT * RS3];
__device__ __align__(16) __half g_xh[MTOT * DD];
__device__ __align__(16) __half g_xl[MTOT * DD];
__device__ __align__(16) __half g_Mh[MTOT * DD];
__device__ __align__(16) __half g_Ml[MTOT * DD];
__device__ __align__(16) __half g_Mth[DD * NBL];
__device__ __align__(16) __half g_Mtl[DD * NBL];
__device__ __align__(16) __half g_Wqkvh[3 * DD * DD];
__device__ __align__(16) __half g_Woh[DD * DD];

// ---------------- small PTX helpers ------------------------------------------
__device__ __forceinline__ uint32_t smem_u32(const void* p) {
    uint32_t a;
    asm("{ .reg .u64 t; cvta.to.shared.u64 t, %1; cvt.u32.u64 %0, t; }"
        : "=r"(a) : "l"(p));
    return a;
}

__device__ __forceinline__ void cp_async16(uint32_t saddr, const void* gptr) {
    asm volatile("cp.async.ca.shared.global [%0], [%1], 16;"
                 :: "r"(saddr), "l"(gptr));
}
__device__ __forceinline__ void cp_commit() {
    asm volatile("cp.async.commit_group;" ::: "memory");
}
template <int N>
__device__ __forceinline__ void cp_wait() {
    asm volatile("cp.async.wait_group %0;" :: "n"(N) : "memory");
}

__device__ __forceinline__ void ldm_x4(uint32_t (&r)[4], uint32_t addr) {
    asm volatile("ldmatrix.sync.aligned.m8n8.x4.shared.b16 {%0,%1,%2,%3}, [%4];"
                 : "=r"(r[0]), "=r"(r[1]), "=r"(r[2]), "=r"(r[3]) : "r"(addr));
}
__device__ __forceinline__ void ldm_x4_trans(uint32_t (&r)[4], uint32_t addr) {
    asm volatile("ldmatrix.sync.aligned.m8n8.x4.trans.shared.b16 {%0,%1,%2,%3}, [%4];"
                 : "=r"(r[0]), "=r"(r[1]), "=r"(r[2]), "=r"(r[3]) : "r"(addr));
}

__device__ __forceinline__ void mma16816(float (&c)[4], const uint32_t (&a)[4],
                                         uint32_t b0, uint32_t b1) {
    asm volatile(
        "mma.sync.aligned.m16n8k16.row.col.f32.f16.f16.f32 "
        "{%0,%1,%2,%3}, {%4,%5,%6,%7}, {%8,%9}, {%0,%1,%2,%3};"
        : "+f"(c[0]), "+f"(c[1]), "+f"(c[2]), "+f"(c[3])
        : "r"(a[0]), "r"(a[1]), "r"(a[2]), "r"(a[3]), "r"(b0), "r"(b1));
}

__device__ __forceinline__ uint32_t pack_h2(__half x, __half y) {
    __half2 h = __halves2half2(x, y);
    return *(uint32_t*)&h;
}

struct __align__(8) half4 { __half a, b, c, d; };

// ---------------- prep mega-kernel: x split + weight rounds + bias concat ----
__global__ __launch_bounds__(256) void prep_kernel(
    const float* __restrict__ x,
    const float* __restrict__ Wq, const float* __restrict__ Wk,
    const float* __restrict__ Wv, const float* __restrict__ Wo,
    const float* __restrict__ bq, const float* __restrict__ bk,
    const float* __restrict__ bv,
    __half* __restrict__ xh, __half* __restrict__ xl,
    __half* __restrict__ Wqkvh, __half* __restrict__ Woh,
    float* __restrict__ bqkv)
{
    int t = blockIdx.x;
    int tid = threadIdx.x;
    if (t < 4096) {
        int i = t * 256 + tid;
        float4 v = ((const float4*)x)[i];
        __half h0 = __float2half_rn(v.x);
        __half h1 = __float2half_rn(v.y);
        __half h2 = __float2half_rn(v.z);
        __half h3 = __float2half_rn(v.w);
        half4 hv = {h0, h1, h2, h3};
        half4 lv = {__float2half_rn(v.x - __half2float(h0)),
                    __float2half_rn(v.y - __half2float(h1)),
                    __float2half_rn(v.z - __half2float(h2)),
                    __float2half_rn(v.w - __half2float(h3))};
        ((half4*)xh)[i] = hv;
        ((half4*)xl)[i] = lv;
    } else if (t < 8192) {
        int wsel = (t - 4096) >> 10;
        int blk = (t - 4096) & 1023;
        const float* src = (wsel == 0) ? Wq : (wsel == 1) ? Wk
                         : (wsel == 2) ? Wv : Wo;
        __half* dst = (wsel < 3) ? (Wqkvh + (size_t)wsel * DD * DD) : Woh;
        int i = blk * 256 + tid;
        float4 v = ((const float4*)src)[i];
        half4 hv = {__float2half_rn(v.x), __float2half_rn(v.y),
                    __float2half_rn(v.z), __float2half_rn(v.w)};
        ((half4*)dst)[i] = hv;
    } else {
        int i = (t - 8192) * 256 + tid;
        if (i < RS3) {
            const float* src = (i < DD) ? bq : (i < 2 * DD) ? bk : bv;
            bqkv[i] = src[i & (DD - 1)];
        }
    }
}

// ---------------- GEMM body ---------------------------------------------------
#define GPITCH 144
#define GTILE  (128 * GPITCH)
#define GBUF   (2 * GTILE)
#define GSMEM  (3 * GBUF)       // 110592 B

__device__ __forceinline__ void gemm_body(
    const __half* __restrict__ Ah, const __half* __restrict__ Al,
    const __half* __restrict__ Bh, const float* __restrict__ bias,
    float* __restrict__ C, float* __restrict__ Cpart,
    __half* __restrict__ Ch, __half* __restrict__ Cl,
    float qscale, int qcols,
    int lda, int Ksl, int N, int M,
    int bx, int by, int split, int nsplit, char* smem)
{
    const uint32_t sbase = smem_u32(smem);
    const int tid = threadIdx.x;
    const int lane = tid & 31;
    const int wid = tid >> 5;
    const int wm = wid >> 2;
    const int wn = wid & 3;

    const __half* pA[2] = {Ah, Al};
    const int Kc = Ksl >> 6;
    const int total = 2 * Kc;

    float c[4][4][4];
#pragma unroll
    for (int i = 0; i < 4; i++)
#pragma unroll
        for (int j = 0; j < 4; j++)
#pragma unroll
            for (int f = 0; f < 4; f++) c[i][j][f] = 0.0f;

    auto load_chunk = [&](int g, int buf) {
        int p = (g >= Kc) ? 1 : 0;
        int kk = g - p * Kc;
        const __half* Abase = pA[p] + (size_t)by * 128 * lda + split * Ksl + kk * 64;
        const __half* Bbase = Bh + (size_t)bx * 128 * lda + split * Ksl + kk * 64;
        uint32_t aS = sbase + buf * GBUF;
        uint32_t bS = aS + GTILE;
#pragma unroll
        for (int j = 0; j < 4; j++) {
            int lin = tid + j * 256;
            int row = lin >> 3;
            int seg = lin & 7;
            cp_async16(aS + row * GPITCH + seg * 16,
                       Abase + (size_t)row * lda + seg * 8);
            cp_async16(bS + row * GPITCH + seg * 16,
                       Bbase + (size_t)row * lda + seg * 8);
        }
        cp_commit();
    };

    load_chunk(0, 0);
    load_chunk(1, 1);

    int buf = 0;
    for (int g = 0; g < total; g++) {
        if (g == total - 1) cp_wait<0>(); else cp_wait<1>();
        __syncthreads();
        if (g + 2 < total) {
            int nb = buf + 2; if (nb >= 3) nb -= 3;
            load_chunk(g + 2, nb);
        }

        const uint32_t aS = sbase + buf * GBUF;
        const uint32_t bS = aS + GTILE;
#pragma unroll
        for (int s = 0; s < 4; s++) {
            uint32_t a[4][4];
#pragma unroll
            for (int i = 0; i < 4; i++) {
                int row = wm * 64 + i * 16 + (lane & 15);
                ldm_x4(a[i], aS + row * GPITCH + s * 32 + ((lane >> 4) * 16));
            }
            uint32_t b[2][4];
#pragma unroll
            for (int j = 0; j < 2; j++) {
                int row = wn * 32 + j * 16 + ((lane >> 4) << 3) + (lane & 7);
                int off = ((lane >> 3) & 1) * 16;
                ldm_x4(b[j], bS + row * GPITCH + s * 32 + off);
            }
#pragma unroll
            for (int i = 0; i < 4; i++) {
#pragma unroll
                for (int j = 0; j < 2; j++) {
                    mma16816(c[i][2 * j], a[i], b[j][0], b[j][1]);
                    mma16816(c[i][2 * j + 1], a[i], b[j][2], b[j][3]);
                }
            }
        }
        if (++buf == 3) buf = 0;
    }

    const bool addb = (bias != nullptr) && (nsplit == 1);
#pragma unroll
    for (int i = 0; i < 4; i++) {
        int r0 = by * 128 + wm * 64 + i * 16 + (lane >> 2);
#pragma unroll
        for (int nt = 0; nt < 4; nt++) {
            int col = bx * 128 + wn * 32 + nt * 8 + (lane & 3) * 2;
            float bx0 = 0.0f, bx1 = 0.0f;
            if (addb) { bx0 = bias[col]; bx1 = bias[col + 1]; }
            float a0 = c[i][nt][0] + bx0, a1 = c[i][nt][1] + bx1;
            float a2 = c[i][nt][2] + bx0, a3 = c[i][nt][3] + bx1;
            if (Ch) {
                float sc = (col < qcols) ? qscale : 1.0f;
                a0 *= sc; a1 *= sc; a2 *= sc; a3 *= sc;
                __half h0 = __float2half_rn(a0), h1 = __float2half_rn(a1);
                __half h2 = __float2half_rn(a2), h3 = __float2half_rn(a3);
                *(__half2*)(Ch + (size_t)r0 * N + col) = __halves2half2(h0, h1);
                *(__half2*)(Ch + (size_t)(r0 + 8) * N + col) = __halves2half2(h2, h3);
                *(__half2*)(Cl + (size_t)r0 * N + col) =
                    __halves2half2(__float2half_rn(a0 - __half2float(h0)),
                                   __float2half_rn(a1 - __half2float(h1)));
                *(__half2*)(Cl + (size_t)(r0 + 8) * N + col) =
                    __halves2half2(__float2half_rn(a2 - __half2float(h2)),
                                   __float2half_rn(a3 - __half2float(h3)));
            } else {
                float* dst = (nsplit == 1) ? C : (Cpart + (size_t)split * M * N);
                float2 v0 = {a0, a1}, v1 = {a2, a3};
                *(float2*)(dst + (size_t)r0 * N + col) = v0;
                *(float2*)(dst + (size_t)(r0 + 8) * N + col) = v1;
            }
        }
    }
}

// ---------------- QKV GEMM kernel --------------------------------------------
__global__ __launch_bounds__(256, 2) void gemm2(
    const __half* __restrict__ Ah, const __half* __restrict__ Al,
    const __half* __restrict__ Bh, const float* __restrict__ bias,
    __half* __restrict__ Ch, __half* __restrict__ Cl,
    float qscale, int qcols, int lda, int Ksl, int N)
{
    extern __shared__ __align__(16) char smem[];
    gemm_body(Ah, Al, Bh, bias, nullptr, nullptr, Ch, Cl, qscale, qcols,
              lda, Ksl, N, gridDim.y * 128,
              blockIdx.x, blockIdx.y, 0, 1, smem);
}

// ---------------- fused mid: out-proj GEMM + symmetric SYRK + colmean --------
// grid: 256 out-proj | 144 syrk (36 upper-tri tiles x split-K 4) | 64 colmean
__global__ __launch_bounds__(256, 2) void fused_mid(
    const __half* __restrict__ Mh, const __half* __restrict__ Ml,
    const __half* __restrict__ Woh, const float* __restrict__ bo,
    float* __restrict__ out,
    const __half* __restrict__ Mth, const __half* __restrict__ Mtl,
    float* __restrict__ Gpart, float* __restrict__ meanpart)
{
    extern __shared__ __align__(16) char smem[];
    int t = blockIdx.x;
    if (t < 256) {
        gemm_body(Mh, Ml, Woh, bo, out, nullptr, nullptr, nullptr, 1.0f, 0,
                  DD, DD, DD, MTOT, t & 7, t >> 3, 0, 1, smem);
    } else if (t < 400) {
        int t2 = t - 256;
        int split = t2 / 36;
        int pair = t2 % 36;
        int ti = 0, s = pair;
        while (s >= 8 - ti) { s -= 8 - ti; ti++; }
        int tj = ti + s;
        // tile (row=ti, col=tj), upper triangle only
        gemm_body(Mth, Mtl, Mth, nullptr, nullptr, Gpart, nullptr, nullptr,
                  1.0f, 0, NBL, NBL / 4, DD, DD,
                  tj, ti, split, 4, smem);
    } else {
        int idx = t - 400;
        int col = (idx & 3) * 256 + threadIdx.x;
        int seg = idx >> 2;
        float s = 0.0f;
        size_t base = (size_t)seg * 256 * DD + col;
#pragma unroll 4
        for (int r = 0; r < 256; r++) {
            size_t o = base + (size_t)r * DD;
            s += __half2float(Mh[o]) + __half2float(Ml[o]);
        }
        meanpart[seg * DD + col] = s;
    }
}

// ---------------- mean finalize ----------------------------------------------
__global__ __launch_bounds__(256) void mean_fin(
    const float* __restrict__ meanpart, float* __restrict__ mean)
{
    int col = blockIdx.x * 256 + threadIdx.x;
    float s = 0.0f;
#pragma unroll
    for (int seg = 0; seg < 16; seg++) s += meanpart[seg * DD + col];
    mean[col] = s * (1.0f / (float)NBL);
}

// ---------------- decov per-tile: reduce Gpart + cov + square ----------------
// grid 144: tile pair (36) x row-quarter (4). Each block: 32 rows x 128 cols.
__global__ __launch_bounds__(256) void decov_tiles(
    const float* __restrict__ Gpart, const float* __restrict__ mean,
    float* __restrict__ partial)
{
    __shared__ float red[256];
    int pair = blockIdx.x % 36;
    int q = blockIdx.x / 36;       // row quarter 0..3
    int ti = 0, s = pair;
    while (s >= 8 - ti) { s -= 8 - ti; ti++; }
    int tj = ti + s;
    const float w = (ti == tj) ? 1.0f : 2.0f;
    const float invN = 1.0f / (float)NBL;

    int row = ti * 128 + q * 32 + (threadIdx.x >> 3);   // 32 rows
    int c0 = tj * 128 + (threadIdx.x & 7) * 16;         // 16 cols each
    float mi = mean[row];
    float acc = 0.0f;
    size_t base = (size_t)row * DD + c0;
#pragma unroll
    for (int c4 = 0; c4 < 4; c4++) {
        int col = c0 + c4 * 4;
        float4 g = *(const float4*)(Gpart + base + c4 * 4);
#pragma unroll
        for (int p = 1; p < 4; p++) {
            float4 v = *(const float4*)(Gpart + (size_t)p * DD * DD + base + c4 * 4);
            g.x += v.x; g.y += v.y; g.z += v.z; g.w += v.w;
        }
        float4 mj = *(const float4*)(mean + col);
        float cx = g.x * invN - mi * mj.x;
        float cy = g.y * invN - mi * mj.y;
        float cz = g.z * invN - mi * mj.z;
        float cw = g.w * invN - mi * mj.w;
        if (row == col) cx = 0.0f;
        if (row == col + 1) cy = 0.0f;
        if (row == col + 2) cz = 0.0f;
        if (row == col + 3) cw = 0.0f;
        acc += cx * cx + cy * cy + cz * cz + cw * cw;
    }
    red[threadIdx.x] = acc * w;
    __syncthreads();
    for (int off = 128; off > 0; off >>= 1) {
        if (threadIdx.x < off) red[threadIdx.x] += red[threadIdx.x + off];
        __syncthreads();
    }
    if (threadIdx.x == 0) partial[blockIdx.x] = red[0];
}

__global__ void decov_final(const float* __restrict__ partial, float* __restrict__ out)
{
    __shared__ float red[144];
    float s = (threadIdx.x < 144) ? partial[threadIdx.x] : 0.0f;
    red[threadIdx.x < 144 ? threadIdx.x : 0] = 0.0f;
    __syncthreads();
    if (threadIdx.x < 144) red[threadIdx.x] = s;
    __syncthreads();
    if (threadIdx.x == 0) {
        float t = 0.0f;
        for (int i = 0; i < 144; i++) t += red[i];
        out[0] = 0.5f * t;
    }
}

// ---------------- Attention: flash + mma.sync, fp16 inputs, cp.async ring ----
#define AP 72
#define APB 144
#define KTB (64 * APB)
#define ASTG (3 * KTB)
#define ASMEM (3 * ASTG)        // 82944 B

__global__ __launch_bounds__(256, 2) void attn_mma(
    const __half* __restrict__ QKVh, const __half* __restrict__ QKVl,
    __half* __restrict__ Oh, __half* __restrict__ Ol)
{
    extern __shared__ __align__(16) char smem[];
    const uint32_t sbase = smem_u32(smem);

    const int tid = threadIdx.x;
    const int lane = tid & 31;
    const int w = tid >> 5;
    const int q0 = blockIdx.x * 128;
    const int h = blockIdx.y;
    const int b = blockIdx.z;

    uint32_t Qah[4][4], Qal[4][4];
    {
        int r0 = b * LL + q0 + w * 16 + (lane >> 2);
        int cb = h * DK + (lane & 3) * 2;
#pragma unroll
        for (int s = 0; s < 4; s++)
#pragma unroll
            for (int t2 = 0; t2 < 4; t2++) {
                size_t off = (size_t)(r0 + (t2 & 1) * 8) * RS3 + cb + s * 16 + (t2 >> 1) * 8;
                Qah[s][t2] = *(const uint32_t*)(QKVh + off);
                Qal[s][t2] = *(const uint32_t*)(QKVl + off);
            }
    }

    auto load_tile = [&](int kt, int stg) {
        uint32_t sb = sbase + stg * ASTG;
#pragma unroll
        for (int it = 0; it < 2; it++) {
            int lin = tid + it * 256;
            int row = lin >> 3;
            int seg = lin & 7;
            size_t goff = (size_t)(b * LL + kt + row) * RS3 + DD + h * DK + seg * 8;
            cp_async16(sb + row * APB + seg * 16, QKVh + goff);
            cp_async16(sb + KTB + row * APB + seg * 16, QKVl + goff);
            cp_async16(sb + 2 * KTB + row * APB + seg * 16, QKVh + goff + DD);
        }
        cp_commit();
    };

    float m0 = -1e30f, m1 = -1e30f, l0 = 0.0f, l1 = 0.0f;
    float co[8][4];
#pragma unroll
    for (int j = 0; j < 8; j++)
#pragma unroll
        for (int f = 0; f < 4; f++) co[j][f] = 0.0f;

    load_tile(0, 0);
    load_tile(64, 1);

    int buf = 0;
    for (int g = 0; g < 16; g++) {
        if (g == 15) cp_wait<0>(); else cp_wait<1>();
        __syncthreads();
        if (g + 2 < 16) {
            int nb = buf + 2; if (nb >= 3) nb -= 3;
            load_tile((g + 2) * 64, nb);
        }
        const uint32_t khs = sbase + buf * ASTG;
        const uint32_t kls = khs + KTB;
        const uint32_t vhs = khs + 2 * KTB;

        float sc[8][4];
#pragma unroll
        for (int j = 0; j < 8; j++)
#pragma unroll
            for (int f = 0; f < 4; f++) sc[j][f] = 0.0f;

#pragma unroll
        for (int s = 0; s < 4; s++) {
#pragma unroll
            for (int j = 0; j < 4; j++) {
                uint32_t roff = (j * 16 + ((lane >> 4) << 3) + (lane & 7)) * APB
                              + s * 32 + ((lane >> 3) & 1) * 16;
                uint32_t bh[4], bl[4];
                ldm_x4(bh, khs + roff);
                ldm_x4(bl, kls + roff);
                mma16816(sc[2 * j],     Qah[s], bh[0], bh[1]);
                mma16816(sc[2 * j + 1], Qah[s], bh[2], bh[3]);
                mma16816(sc[2 * j],     Qal[s], bh[0], bh[1]);
                mma16816(sc[2 * j + 1], Qal[s], bh[2], bh[3]);
                mma16816(sc[2 * j],     Qah[s], bl[0], bl[1]);
                mma16816(sc[2 * j + 1], Qah[s], bl[2], bl[3]);
            }
        }

        float t0 = -1e30f, t1 = -1e30f;
#pragma unroll
        for (int j = 0; j < 8; j++) {
            t0 = fmaxf(t0, fmaxf(sc[j][0], sc[j][1]));
            t1 = fmaxf(t1, fmaxf(sc[j][2], sc[j][3]));
        }
        t0 = fmaxf(t0, __shfl_xor_sync(0xffffffffu, t0, 1));
        t0 = fmaxf(t0, __shfl_xor_sync(0xffffffffu, t0, 2));
        t1 = fmaxf(t1, __shfl_xor_sync(0xffffffffu, t1, 1));
        t1 = fmaxf(t1, __shfl_xor_sync(0xffffffffu, t1, 2));
        float mn0 = fmaxf(m0, t0), mn1 = fmaxf(m1, t1);
        float f0 = __expf(m0 - mn0), f1 = __expf(m1 - mn1);
        float rs0 = 0.0f, rs1 = 0.0f;
#pragma unroll
        for (int j = 0; j < 8; j++) {
            sc[j][0] = __expf(sc[j][0] - mn0);
            sc[j][1] = __expf(sc[j][1] - mn0);
            sc[j][2] = __expf(sc[j][2] - mn1);
            sc[j][3] = __expf(sc[j][3] - mn1);
            rs0 += sc[j][0] + sc[j][1];
            rs1 += sc[j][2] + sc[j][3];
        }
        rs0 += __shfl_xor_sync(0xffffffffu, rs0, 1);
        rs0 += __shfl_xor_sync(0xffffffffu, rs0, 2);
        rs1 += __shfl_xor_sync(0xffffffffu, rs1, 1);
        rs1 += __shfl_xor_sync(0xffffffffu, rs1, 2);
        l0 = l0 * f0 + rs0;
        l1 = l1 * f1 + rs1;
        m0 = mn0; m1 = mn1;
#pragma unroll
        for (int j = 0; j < 8; j++) {
            co[j][0] *= f0; co[j][1] *= f0;
            co[j][2] *= f1; co[j][3] *= f1;
        }

#pragma unroll
        for (int s = 0; s < 4; s++) {
            uint32_t pah[4], pal[4];
#pragma unroll
            for (int t2 = 0; t2 < 4; t2++) {
                int bk = 2 * s + (t2 >> 1);
                float p0 = sc[bk][(t2 & 1) * 2];
                float p1 = sc[bk][(t2 & 1) * 2 + 1];
                __half h0 = __float2half_rn(p0), h1 = __float2half_rn(p1);
                pah[t2] = pack_h2(h0, h1);
                pal[t2] = pack_h2(__float2half_rn(p0 - __half2float(h0)),
                                  __float2half_rn(p1 - __half2float(h1)));
            }
#pragma unroll
            for (int j = 0; j < 4; j++) {
                uint32_t roff = (s * 16 + ((lane >> 3) & 1) * 8 + (lane & 7)) * APB
                              + (j * 16 + ((lane >> 4) & 1) * 8) * 2;
                uint32_t vbh[4];
                ldm_x4_trans(vbh, vhs + roff);
                mma16816(co[2 * j],     pah, vbh[0], vbh[1]);
                mma16816(co[2 * j + 1], pah, vbh[2], vbh[3]);
                mma16816(co[2 * j],     pal, vbh[0], vbh[1]);
                mma16816(co[2 * j + 1], pal, vbh[2], vbh[3]);
            }
        }
        if (++buf == 3) buf = 0;
    }

    float inv0 = 1.0f / l0, inv1 = 1.0f / l1;
    int grow = q0 + w * 16 + (lane >> 2);
    size_t base0 = (size_t)(b * LL + grow) * DD + h * DK;
    size_t base1 = base0 + (size_t)8 * DD;
#pragma unroll
    for (int j = 0; j < 8; j++) {
        int col = j * 8 + (lane & 3) * 2;
        float a0 = co[j][0] * inv0, a1 = co[j][1] * inv0;
        float a2 = co[j][2] * inv1, a3 = co[j][3] * inv1;
        __half h0 = __float2half_rn(a0), h1 = __float2half_rn(a1);
        __half h2 = __float2half_rn(a2), h3 = __float2half_rn(a3);
        *(__half2*)(Oh + base0 + col) = __halves2half2(h0, h1);
        *(__half2*)(Oh + base1 + col) = __halves2half2(h2, h3);
        *(__half2*)(Ol + base0 + col) =
            __halves2half2(__float2half_rn(a0 - __half2float(h0)),
                           __float2half_rn(a1 - __half2float(h1)));
        *(__half2*)(Ol + base1 + col) =
            __halves2half2(__float2half_rn(a2 - __half2float(h2)),
                           __float2half_rn(a3 - __half2float(h3)));
    }
}

// ---------------- transpose + split: (Mh+Ml)[NBL][DD] -> T[DD][NBL] ----------
__global__ __launch_bounds__(256) void transpose_split_fp16(
    const __half* __restrict__ Msh, const __half* __restrict__ Msl,
    __half* __restrict__ Th, __half* __restrict__ Tl)
{
    __shared__ float tile[32][33];
    int bx = blockIdx.x;
    int by = blockIdx.y;
    int tx = threadIdx.x;
    int ty = threadIdx.y;
#pragma unroll
    for (int j = 0; j < 32; j += 8) {
        size_t off = (size_t)(by * 32 + ty + j) * DD + bx * 32 + tx;
        tile[ty + j][tx] = __half2float(Msh[off]) + __half2float(Msl[off]);
    }
    __syncthreads();
#pragma unroll
    for (int j = 0; j < 32; j += 8) {
        float v = tile[tx][ty + j];
        __half h = __float2half_rn(v);
        __half l = __float2half_rn(v - __half2float(h));
        size_t off = (size_t)(bx * 32 + ty + j) * NBL + by * 32 + tx;
        Th[off] = h;
        Tl[off] = l;
    }
}

// ---------------- launch ------------------------------------------------------
extern "C" void kernel_launch(void* const* d_in, const int* in_sizes, int n_in,
                              void* d_out, int out_size)
{
    const float* x  = (const float*)d_in[0];
    const float* Wq = (const float*)d_in[1];
    const float* bq = (const float*)d_in[2];
    const float* Wk = (const float*)d_in[3];
    const float* bk = (const float*)d_in[4];
    const float* Wv = (const float*)d_in[5];
    const float* bv = (const float*)d_in[6];
    const float* Wo = (const float*)d_in[7];
    const float* bo = (const float*)d_in[8];
    float* out = (float*)d_out;

    float *meanp, *meanpartp, *partp, *Gpart, *bqkv;
    cudaGetSymbolAddress((void**)&meanp, g_mean);
    cudaGetSymbolAddress((void**)&meanpartp, g_meanpart);
    cudaGetSymbolAddress((void**)&partp, g_partial);
    cudaGetSymbolAddress((void**)&Gpart, g_Gpart);
    cudaGetSymbolAddress((void**)&bqkv, g_bqkv);

    __half *QKVh, *QKVl, *xh, *xl, *Mh, *Ml, *Mth, *Mtl, *Wqkvh, *Woh;
    cudaGetSymbolAddress((void**)&QKVh, g_QKVh);
    cudaGetSymbolAddress((void**)&QKVl, g_QKVl);
    cudaGetSymbolAddress((void**)&xh, g_xh);
    cudaGetSymbolAddress((void**)&xl, g_xl);
    cudaGetSymbolAddress((void**)&Mh, g_Mh);
    cudaGetSymbolAddress((void**)&Ml, g_Ml);
    cudaGetSymbolAddress((void**)&Mth, g_Mth);
    cudaGetSymbolAddress((void**)&Mtl, g_Mtl);
    cudaGetSymbolAddress((void**)&Wqkvh, g_Wqkvh);
    cudaGetSymbolAddress((void**)&Woh, g_Woh);

    cudaFuncSetAttribute(gemm2, cudaFuncAttributeMaxDynamicSharedMemorySize,
                         GSMEM);
    cudaFuncSetAttribute(fused_mid, cudaFuncAttributeMaxDynamicSharedMemorySize,
                         GSMEM);
    cudaFuncSetAttribute(attn_mma, cudaFuncAttributeMaxDynamicSharedMemorySize,
                         ASMEM);

    // 1. prep
    prep_kernel<<<8204, 256>>>(x, Wq, Wk, Wv, Wo, bq, bk, bv,
                               xh, xl, Wqkvh, Woh, bqkv);

    // 2. fused QKV projection
    dim3 gQKV(RS3 / 128, MTOT / 128, 1);
    gemm2<<<gQKV, 256, GSMEM>>>(xh, xl, Wqkvh, bqkv,
                                QKVh, QKVl, 0.125f, DD, DD, DD, RS3);

    // 3. attention
    dim3 gAttn(LL / 128, HH, BB);
    attn_mma<<<gAttn, 256, ASMEM>>>(QKVh, QKVl, Mh, Ml);

    // 4. transposed split of M
    transpose_split_fp16<<<dim3(DD / 32, NBL / 32), dim3(32, 8)>>>(Mh, Ml, Mth, Mtl);

    // 5. fused: out-proj (256) + symmetric SYRK (144) + colmean-part (64)
    fused_mid<<<464, 256, GSMEM>>>(Mh, Ml, Woh, bo, out,
                                   Mth, Mtl, Gpart, meanpartp);

    // 6. mean finalize
    mean_fin<<<4, 256>>>(meanpartp, meanp);

    // 7. decov per-tile (reduce Gpart + covariance + square)
    decov_tiles<<<144, 256>>>(Gpart, meanp, partp);

    // 8. final scalar
    decov_final<<<1, 256>>>(partp, out + (out_size - 1));
}